// round 7
// baseline (speedup 1.0000x reference)
#include <cuda_runtime.h>
#include <math.h>

#define NN 50000
#define NE 800000
#define KIN 128
#define F 64
#define NF (NN*F)
#define SCAN_B 512
#define NBLK ((NN + SCAN_B - 1) / SCAN_B)   // 98

// ---- scratch (device globals; no allocation allowed) ----
__device__ __align__(16) float g_self[NF];
__device__ __align__(16) float g_bsum[NF];
__device__ __align__(16) float g_esum[NF];
__device__ __align__(16) float g_bmax[NF];
__device__ __align__(16) float g_emax[NF];
__device__ __align__(16) float g_segmax[NF];
__device__ __align__(16) float g_sumagg[NF];

__device__ int d_deg[NN];
__device__ int d_row[NN + 1];
__device__ int d_cur[NN];
__device__ int d_bsumI[NBLK];
__device__ int d_boff[NBLK];
__device__ int d_ei[NE];          // end ids sorted by begin id

// B pre-packed in MMA fragment lane order, tf32-converted.
// index: ((((slice*8 + kc)*2 + ks)*8 + nbk)*32 + lane)*2 floats
__device__ __align__(16) float d_B2[5 * 8 * 2 * 8 * 32 * 2];

__device__ __align__(16) float d_sum_s[64];
__device__ __align__(16) float d_ss_s[64];
__device__ __align__(16) float d_mu_s[64];
__device__ __align__(16) float d_istd_s[64];
__device__ __align__(16) float d_sum_g[128];
__device__ __align__(16) float d_ss_g[128];
__device__ __align__(16) float d_a_g[128];
__device__ __align__(16) float d_c_g[128];
__device__ __align__(16) float d_Wp[128 * 64];
__device__ __align__(16) float d_doff[64];
__device__ int   d_min_i;

// ---- monotone float<->int key ----
__device__ __forceinline__ int fkey(float f) {
    int i = __float_as_int(f);
    return i >= 0 ? i : (i ^ 0x7fffffff);
}
__device__ __forceinline__ float fdec(int k) {
    return __int_as_float(k >= 0 ? k : (k ^ 0x7fffffff));
}

// tf32 cvt: PTX requires .b32 destination register
__device__ __forceinline__ float to_tf32(float v) {
    unsigned r;
    asm("cvt.rna.tf32.f32 %0, %1;" : "=r"(r) : "f"(v));
    return __uint_as_float(r);
}
__device__ __forceinline__ float4 to_tf32_4(float4 v) {
    float4 r;
    r.x = to_tf32(v.x); r.y = to_tf32(v.y);
    r.z = to_tf32(v.z); r.w = to_tf32(v.w);
    return r;
}

// ---- K0: init small scratch ----
__global__ void k_init() {
    int i = blockIdx.x * blockDim.x + threadIdx.x;
    int stride = gridDim.x * blockDim.x;
    for (int j = i; j < NN; j += stride) d_deg[j] = 0;
    if (i < 64)  { d_sum_s[i] = 0.0f; d_ss_s[i] = 0.0f; }
    if (i < 128) { d_sum_g[i] = 0.0f; d_ss_g[i] = 0.0f; }
    if (i == 0)  d_min_i = INT_MAX;
}

// ---- CSR build ----
__global__ void k_deg(const int* __restrict__ b) {
    int i = blockIdx.x * blockDim.x + threadIdx.x;
    int stride = gridDim.x * blockDim.x;
    for (; i < NE; i += stride) atomicAdd(&d_deg[b[i]], 1);
}

// ---- pre-pack B into fragment lane order (tf32) ----
__global__ void k_prepB(const float* __restrict__ B) {  // [128,320]
    int idx = blockIdx.x * blockDim.x + threadIdx.x;    // 0..40959
    if (idx >= 5 * 8 * 2 * 8 * 32) return;
    int lane = idx & 31;
    int t = idx >> 5;
    int nbk = t & 7;  t >>= 3;
    int ks  = t & 1;  t >>= 1;
    int kc  = t & 7;  t >>= 3;
    int slice = t;                      // 0..4
    int g = lane >> 2, tig = lane & 3;
    int k = kc * 16 + ks * 8 + tig;
    int n = slice * 64 + nbk * 8 + g;
    float2 v;
    v.x = to_tf32(B[k * 320 + n]);
    v.y = to_tf32(B[(k + 4) * 320 + n]);
    *(float2*)&d_B2[idx * 2] = v;
}

__global__ void k_scan1() {
    __shared__ int sh[SCAN_B];
    int i = blockIdx.x * SCAN_B + threadIdx.x;
    sh[threadIdx.x] = (i < NN) ? d_deg[i] : 0;
    __syncthreads();
    for (int off = SCAN_B / 2; off; off >>= 1) {
        if (threadIdx.x < off) sh[threadIdx.x] += sh[threadIdx.x + off];
        __syncthreads();
    }
    if (threadIdx.x == 0) d_bsumI[blockIdx.x] = sh[0];
}

__global__ void k_scan2() {
    int t = threadIdx.x;
    int v = (t < NBLK) ? d_bsumI[t] : 0;
    int x = v;
    #pragma unroll
    for (int off = 1; off < 32; off <<= 1) {
        int y = __shfl_up_sync(0xffffffffu, x, off);
        if ((t & 31) >= off) x += y;
    }
    __shared__ int wt[4];
    if ((t & 31) == 31) wt[t >> 5] = x;
    __syncthreads();
    int add = 0;
    for (int w = 0; w < (t >> 5); w++) add += wt[w];
    x += add;
    if (t < NBLK) d_boff[t] = x - v;
    if (t == 0) d_row[NN] = NE;
}

__global__ void k_scan3() {
    int t = threadIdx.x;
    int lane = t & 31, w = t >> 5;
    int i = blockIdx.x * SCAN_B + t;
    int v = (i < NN) ? d_deg[i] : 0;
    int x = v;
    #pragma unroll
    for (int off = 1; off < 32; off <<= 1) {
        int y = __shfl_up_sync(0xffffffffu, x, off);
        if (lane >= off) x += y;
    }
    __shared__ int wt[16];
    if (lane == 31) wt[w] = x;
    __syncthreads();
    int add = d_boff[blockIdx.x];
    for (int k = 0; k < w; k++) add += wt[k];
    int excl = x - v + add;
    if (i < NN) { d_row[i] = excl; d_cur[i] = excl; }
}

__global__ void k_fill(const int* __restrict__ b, const int* __restrict__ e) {
    int i = blockIdx.x * blockDim.x + threadIdx.x;
    int stride = gridDim.x * blockDim.x;
    for (; i < NE; i += stride) {
        int pos = atomicAdd(&d_cur[b[i]], 1);
        d_ei[pos] = e[i];
    }
}

// ---- K1: GEMM1 tf32 mma.sync, A double-buffered in smem, B from d_B2 (L2) ----
// Block 256 thr, tile 256(M) x 64(N), K chunks of 16, warp tile 64x32.
__global__ void __launch_bounds__(256, 2)
k_gemm1(const float* __restrict__ A,    // [NN,128]
        const float* __restrict__ bias) // [320]
{
    __shared__ __align__(16) float As[2][256][20];
    int tid = threadIdx.x;
    int lane = tid & 31, wid = tid >> 5;
    int wm = wid & 3, wn = wid >> 2;     // warp tile origin: (wm*64, wn*32)
    int g = lane >> 2, tig = lane & 3;
    int m0 = blockIdx.x * 256;
    int nb = blockIdx.y;                 // slice

    float c[4][4][4];
    #pragma unroll
    for (int mt = 0; mt < 4; mt++)
        #pragma unroll
        for (int nt = 0; nt < 4; nt++)
            #pragma unroll
            for (int i = 0; i < 4; i++) c[mt][nt][i] = 0.0f;

    // A fill mapping: 4 passes of 64 rows; 4 threads per row
    int frow = tid >> 2;            // 0..63
    int fc = (tid & 3) * 4;         // 0,4,8,12

    // fill chunk 0
    #pragma unroll
    for (int p = 0; p < 4; p++) {
        int row = p * 64 + frow;
        int gm = m0 + row;
        float4 v = make_float4(0.f, 0.f, 0.f, 0.f);
        if (gm < NN) v = *(const float4*)&A[gm * KIN + fc];
        *(float4*)&As[0][row][fc] = to_tf32_4(v);
    }
    __syncthreads();

    const float* b2base = &d_B2[(nb * 8) * 2 * 8 * 64];

    #pragma unroll
    for (int kci = 0; kci < 8; kci++) {
        int cur = kci & 1;
        float4 pf[4];
        if (kci < 7) {
            int kc = (kci + 1) * 16;
            #pragma unroll
            for (int p = 0; p < 4; p++) {
                int gm = m0 + p * 64 + frow;
                pf[p] = make_float4(0.f, 0.f, 0.f, 0.f);
                if (gm < NN) pf[p] = *(const float4*)&A[gm * KIN + kc + fc];
            }
        }

        #pragma unroll
        for (int ks = 0; ks < 2; ks++) {
            int kk = ks * 8 + tig;
            unsigned af[4][4];
            #pragma unroll
            for (int mt = 0; mt < 4; mt++) {
                int mr = wm * 64 + mt * 16;
                af[mt][0] = __float_as_uint(As[cur][mr + g][kk]);
                af[mt][1] = __float_as_uint(As[cur][mr + g + 8][kk]);
                af[mt][2] = __float_as_uint(As[cur][mr + g][kk + 4]);
                af[mt][3] = __float_as_uint(As[cur][mr + g + 8][kk + 4]);
            }
            #pragma unroll
            for (int nt = 0; nt < 4; nt++) {
                int nbk = wn * 4 + nt;
                float2 bf = *(const float2*)&b2base[(((kci * 2) + ks) * 8 + nbk) * 64 + lane * 2];
                unsigned b0 = __float_as_uint(bf.x);
                unsigned b1 = __float_as_uint(bf.y);
                #pragma unroll
                for (int mt = 0; mt < 4; mt++) {
                    asm volatile(
                        "mma.sync.aligned.m16n8k8.row.col.f32.tf32.tf32.f32 "
                        "{%0,%1,%2,%3}, {%4,%5,%6,%7}, {%8,%9}, {%0,%1,%2,%3};"
                        : "+f"(c[mt][nt][0]), "+f"(c[mt][nt][1]),
                          "+f"(c[mt][nt][2]), "+f"(c[mt][nt][3])
                        : "r"(af[mt][0]), "r"(af[mt][1]), "r"(af[mt][2]), "r"(af[mt][3]),
                          "r"(b0), "r"(b1));
                }
            }
        }

        if (kci < 7) {
            #pragma unroll
            for (int p = 0; p < 4; p++)
                *(float4*)&As[cur ^ 1][p * 64 + frow][fc] = to_tf32_4(pf[p]);
        }
        __syncthreads();
    }

    int n0 = nb * 64;
    float* outp = (nb == 0) ? g_self : (nb == 1) ? g_bsum :
                  (nb == 2) ? g_esum : (nb == 3) ? g_bmax : g_emax;
    #pragma unroll
    for (int mt = 0; mt < 4; mt++) {
        #pragma unroll
        for (int nt = 0; nt < 4; nt++) {
            int col = wn * 32 + nt * 8 + tig * 2;
            float bx = bias[n0 + col], by = bias[n0 + col + 1];
            int r0 = m0 + wm * 64 + mt * 16 + g;
            if (r0 < NN) {
                float2 o; o.x = c[mt][nt][0] + bx; o.y = c[mt][nt][1] + by;
                *(float2*)&outp[r0 * 64 + col] = o;
            }
            int r1 = r0 + 8;
            if (r1 < NN) {
                float2 o; o.x = c[mt][nt][2] + bx; o.y = c[mt][nt][3] + by;
                *(float2*)&outp[r1 * 64 + col] = o;
            }
        }
    }
}

// ---- pass A: segment max + edge-BN stats + global min. 2 edges/warp, float4 lanes ----
__global__ void k_edgeA() {
    __shared__ float s_acc[128];
    __shared__ int s_min;
    int tid = threadIdx.x;
    int lane = tid & 31;
    int half = lane >> 4, q = lane & 15;   // feats 4q..4q+3, edge parity half
    if (tid < 128) s_acc[tid] = 0.0f;
    if (tid == 0) s_min = INT_MAX;
    __syncthreads();

    int warp = (blockIdx.x * blockDim.x + tid) >> 5;
    int nwarp = (gridDim.x * blockDim.x) >> 5;
    float4 as = make_float4(0.f, 0.f, 0.f, 0.f);
    float4 aq = make_float4(0.f, 0.f, 0.f, 0.f);
    float lmin = INFINITY;

    for (int n = warp; n < NN; n += nwarp) {
        int beg = d_row[n], end = d_row[n + 1];
        float4 bs = *(const float4*)&g_bsum[n * 64 + 4 * q];
        float4 bm = *(const float4*)&g_bmax[n * 64 + 4 * q];
        float4 mx = make_float4(-INFINITY, -INFINITY, -INFINITY, -INFINITY);
        #pragma unroll 2
        for (int e = beg; e < end; e += 2) {
            int myE = e + half;
            if (myE < end) {
                int ei = d_ei[myE];
                float4 es = *(const float4*)&g_esum[ei * 64 + 4 * q];
                float4 em = *(const float4*)&g_emax[ei * 64 + 4 * q];
                float s0 = bs.x + es.x, s1 = bs.y + es.y;
                float s2 = bs.z + es.z, s3 = bs.w + es.w;
                as.x += s0; as.y += s1; as.z += s2; as.w += s3;
                aq.x += s0 * s0; aq.y += s1 * s1; aq.z += s2 * s2; aq.w += s3 * s3;
                float m0 = bm.x + em.x, m1 = bm.y + em.y;
                float m2 = bm.z + em.z, m3 = bm.w + em.w;
                mx.x = fmaxf(mx.x, m0); mx.y = fmaxf(mx.y, m1);
                mx.z = fmaxf(mx.z, m2); mx.w = fmaxf(mx.w, m3);
                lmin = fminf(lmin, fminf(fminf(m0, m1), fminf(m2, m3)));
            }
        }
        mx.x = fmaxf(mx.x, __shfl_xor_sync(0xffffffffu, mx.x, 16));
        mx.y = fmaxf(mx.y, __shfl_xor_sync(0xffffffffu, mx.y, 16));
        mx.z = fmaxf(mx.z, __shfl_xor_sync(0xffffffffu, mx.z, 16));
        mx.w = fmaxf(mx.w, __shfl_xor_sync(0xffffffffu, mx.w, 16));
        if (half == 0)
            *(float4*)&g_segmax[n * 64 + 4 * q] = mx;   // -INF if empty; fixed in k_node
    }

    atomicAdd(&s_acc[4 * q + 0], as.x);
    atomicAdd(&s_acc[4 * q + 1], as.y);
    atomicAdd(&s_acc[4 * q + 2], as.z);
    atomicAdd(&s_acc[4 * q + 3], as.w);
    atomicAdd(&s_acc[64 + 4 * q + 0], aq.x);
    atomicAdd(&s_acc[64 + 4 * q + 1], aq.y);
    atomicAdd(&s_acc[64 + 4 * q + 2], aq.z);
    atomicAdd(&s_acc[64 + 4 * q + 3], aq.w);
    #pragma unroll
    for (int off = 16; off; off >>= 1)
        lmin = fminf(lmin, __shfl_xor_sync(0xffffffffu, lmin, off));
    if (lane == 0) atomicMin(&s_min, fkey(lmin));
    __syncthreads();
    if (tid < 64) {
        atomicAdd(&d_sum_s[tid], s_acc[tid]);
        atomicAdd(&d_ss_s[tid], s_acc[64 + tid]);
    }
    if (tid == 0) atomicMin(&d_min_i, s_min);
}

__global__ void k_fin_s() {
    int t = threadIdx.x;  // 64
    float mu = d_sum_s[t] / (float)NE;
    float var = d_ss_s[t] / (float)NE - mu * mu;
    d_mu_s[t] = mu;
    d_istd_s[t] = rsqrtf(var + 1e-5f);
}

// ---- pass B: per-node relu(bn(ef_sum)) sum + node-BN stats. 2 edges/warp ----
__global__ void k_edgeB(const float* __restrict__ gamma,
                        const float* __restrict__ beta) {
    __shared__ float s_acc[128];
    int tid = threadIdx.x;
    int lane = tid & 31;
    int half = lane >> 4, q = lane & 15;
    if (tid < 128) s_acc[tid] = 0.0f;
    __syncthreads();

    float a0 = d_istd_s[4 * q + 0] * gamma[4 * q + 0];
    float a1 = d_istd_s[4 * q + 1] * gamma[4 * q + 1];
    float a2 = d_istd_s[4 * q + 2] * gamma[4 * q + 2];
    float a3 = d_istd_s[4 * q + 3] * gamma[4 * q + 3];
    float c0 = beta[4 * q + 0] - d_mu_s[4 * q + 0] * a0;
    float c1 = beta[4 * q + 1] - d_mu_s[4 * q + 1] * a1;
    float c2 = beta[4 * q + 2] - d_mu_s[4 * q + 2] * a2;
    float c3 = beta[4 * q + 3] - d_mu_s[4 * q + 3] * a3;

    int warp = (blockIdx.x * blockDim.x + tid) >> 5;
    int nwarp = (gridDim.x * blockDim.x) >> 5;
    float4 ns = make_float4(0.f, 0.f, 0.f, 0.f);
    float4 nq = make_float4(0.f, 0.f, 0.f, 0.f);

    for (int n = warp; n < NN; n += nwarp) {
        int beg = d_row[n], end = d_row[n + 1];
        float4 bs = *(const float4*)&g_bsum[n * 64 + 4 * q];
        float4 acc = make_float4(0.f, 0.f, 0.f, 0.f);
        #pragma unroll 2
        for (int e = beg; e < end; e += 2) {
            int myE = e + half;
            if (myE < end) {
                int ei = d_ei[myE];
                float4 es = *(const float4*)&g_esum[ei * 64 + 4 * q];
                acc.x += fmaxf(0.f, fmaf(bs.x + es.x, a0, c0));
                acc.y += fmaxf(0.f, fmaf(bs.y + es.y, a1, c1));
                acc.z += fmaxf(0.f, fmaf(bs.z + es.z, a2, c2));
                acc.w += fmaxf(0.f, fmaf(bs.w + es.w, a3, c3));
            }
        }
        acc.x += __shfl_xor_sync(0xffffffffu, acc.x, 16);
        acc.y += __shfl_xor_sync(0xffffffffu, acc.y, 16);
        acc.z += __shfl_xor_sync(0xffffffffu, acc.z, 16);
        acc.w += __shfl_xor_sync(0xffffffffu, acc.w, 16);
        if (half == 0) {
            *(float4*)&g_sumagg[n * 64 + 4 * q] = acc;
            ns.x += acc.x; ns.y += acc.y; ns.z += acc.z; ns.w += acc.w;
            nq.x += acc.x * acc.x; nq.y += acc.y * acc.y;
            nq.z += acc.z * acc.z; nq.w += acc.w * acc.w;
        }
    }

    if (half == 0) {
        atomicAdd(&s_acc[4 * q + 0], ns.x);
        atomicAdd(&s_acc[4 * q + 1], ns.y);
        atomicAdd(&s_acc[4 * q + 2], ns.z);
        atomicAdd(&s_acc[4 * q + 3], ns.w);
        atomicAdd(&s_acc[64 + 4 * q + 0], nq.x);
        atomicAdd(&s_acc[64 + 4 * q + 1], nq.y);
        atomicAdd(&s_acc[64 + 4 * q + 2], nq.z);
        atomicAdd(&s_acc[64 + 4 * q + 3], nq.w);
    }
    __syncthreads();
    if (tid < 64) {
        atomicAdd(&d_sum_g[64 + tid], s_acc[tid]);
        atomicAdd(&d_ss_g[64 + tid], s_acc[64 + tid]);
    }
}

// ---- K5: empty-segment fix + node-BN stats for segmax half ----
__global__ void k_node() {
    __shared__ float s_acc[128];
    int tid = threadIdx.x;
    int lane = tid & 31;
    if (tid < 128) s_acc[tid] = 0.0f;
    __syncthreads();

    int f0 = 2 * lane;
    float minv = fdec(d_min_i);
    int warp = (blockIdx.x * blockDim.x + tid) >> 5;
    int nwarp = (gridDim.x * blockDim.x) >> 5;
    float nsx = 0.f, nsy = 0.f, nqx = 0.f, nqy = 0.f;
    for (int n = warp; n < NN; n += nwarp) {
        float2 v = *(const float2*)&g_segmax[n * 64 + f0];
        if (v.x == -INFINITY) {
            v.x = minv; v.y = minv;
            *(float2*)&g_segmax[n * 64 + f0] = v;
        }
        nsx += v.x; nsy += v.y;
        nqx += v.x * v.x; nqy += v.y * v.y;
    }
    atomicAdd(&s_acc[f0], nsx);
    atomicAdd(&s_acc[f0 + 1], nsy);
    atomicAdd(&s_acc[64 + f0], nqx);
    atomicAdd(&s_acc[64 + f0 + 1], nqy);
    __syncthreads();
    if (tid < 64) {
        atomicAdd(&d_sum_g[tid], s_acc[tid]);
        atomicAdd(&d_ss_g[tid], s_acc[64 + tid]);
    }
}

__global__ void k_fin_g(const float* __restrict__ gamma_u,
                        const float* __restrict__ beta_u,
                        const float* __restrict__ W_u) {
    int t = threadIdx.x;  // 256
    if (t < 128) {
        float mu = d_sum_g[t] / (float)NN;
        float var = d_ss_g[t] / (float)NN - mu * mu;
        float a = rsqrtf(var + 1e-5f) * gamma_u[t];
        d_a_g[t] = a;
        d_c_g[t] = beta_u[t] - mu * a;
    }
    __syncthreads();
    for (int idx = t; idx < 128 * 64; idx += 256)
        d_Wp[idx] = d_a_g[idx >> 6] * W_u[idx];
    if (t < 64) {
        float acc = 0.f;
        for (int k = 0; k < 128; k++) acc += d_c_g[k] * W_u[k * 64 + t];
        d_doff[t] = acc;
    }
}

// ---- K7: out = self + relu(g_raw @ W' + doff) ----
__global__ void k_final(float* __restrict__ out) {
    __shared__ __align__(16) float Ws[128 * 64];
    __shared__ float Ds[64];
    __shared__ float Gs[8][2][128];
    int tid = threadIdx.x;
    int lane = tid & 31, w = tid >> 5;
    for (int i = tid; i < 128 * 64; i += 256) Ws[i] = d_Wp[i];
    if (tid < 64) Ds[tid] = d_doff[tid];
    __syncthreads();

    int pair = blockIdx.x * 8 + w;
    int pstride = gridDim.x * 8;
    for (int p = pair; p < NN / 2; p += pstride) {
        int nA = 2 * p, nB = 2 * p + 1;
        Gs[w][0][lane]      = g_segmax[nA * 64 + lane];
        Gs[w][0][lane + 32] = g_segmax[nA * 64 + lane + 32];
        Gs[w][0][64 + lane] = g_sumagg[nA * 64 + lane];
        Gs[w][0][96 + lane] = g_sumagg[nA * 64 + lane + 32];
        Gs[w][1][lane]      = g_segmax[nB * 64 + lane];
        Gs[w][1][lane + 32] = g_segmax[nB * 64 + lane + 32];
        Gs[w][1][64 + lane] = g_sumagg[nB * 64 + lane];
        Gs[w][1][96 + lane] = g_sumagg[nB * 64 + lane + 32];
        __syncwarp();
        float a0 = 0.f, a1 = 0.f, b0 = 0.f, b1 = 0.f;
        #pragma unroll 4
        for (int k = 0; k < 128; k++) {
            float ga = Gs[w][0][k], gb = Gs[w][1][k];
            float w0 = Ws[k * 64 + lane], w1 = Ws[k * 64 + lane + 32];
            a0 += ga * w0; a1 += ga * w1;
            b0 += gb * w0; b1 += gb * w1;
        }
        out[nA * 64 + lane]      = g_self[nA * 64 + lane]      + fmaxf(0.f, a0 + Ds[lane]);
        out[nA * 64 + lane + 32] = g_self[nA * 64 + lane + 32] + fmaxf(0.f, a1 + Ds[lane + 32]);
        out[nB * 64 + lane]      = g_self[nB * 64 + lane]      + fmaxf(0.f, b0 + Ds[lane]);
        out[nB * 64 + lane + 32] = g_self[nB * 64 + lane + 32] + fmaxf(0.f, b1 + Ds[lane + 32]);
        __syncwarp();
    }
}

extern "C" void kernel_launch(void* const* d_in, const int* in_sizes, int n_in,
                              void* d_out, int out_size) {
    const float* n_feat  = (const float*)d_in[0];
    const int*   eidx    = (const int*)d_in[1];
    const float* W_b     = (const float*)d_in[2];
    const float* b_b     = (const float*)d_in[3];
    const float* gamma_g = (const float*)d_in[4];
    const float* beta_g  = (const float*)d_in[5];
    const float* gamma_u = (const float*)d_in[6];
    const float* beta_u  = (const float*)d_in[7];
    const float* W_u     = (const float*)d_in[8];
    float* out           = (float*)d_out;

    const int* begin_ids = eidx;
    const int* end_ids   = eidx + NE;

    k_init<<<256, 256>>>();
    k_deg<<<1184, 256>>>(begin_ids);
    k_prepB<<<160, 256>>>(W_b);
    // gemm1 at launch index 3 (0-based): ncu capture slot
    dim3 g1((NN + 255) / 256, 5);
    k_gemm1<<<g1, 256>>>(n_feat, b_b);
    k_scan1<<<NBLK, SCAN_B>>>();
    k_scan2<<<1, 128>>>();
    k_scan3<<<NBLK, SCAN_B>>>();
    k_fill<<<1184, 256>>>(begin_ids, end_ids);
    k_edgeA<<<1184, 256>>>();
    k_fin_s<<<1, 64>>>();
    k_edgeB<<<1184, 256>>>(gamma_g, beta_g);
    k_node<<<1184, 256>>>();
    k_fin_g<<<1, 256>>>(gamma_u, beta_u, W_u);
    k_final<<<1184, 256>>>(out);
}

// round 8
// speedup vs baseline: 1.1430x; 1.1430x over previous
#include <cuda_runtime.h>
#include <math.h>

#define NN 50000
#define NE 800000
#define KIN 128
#define F 64
#define NF (NN*F)
#define SCAN_B 512
#define NBLK ((NN + SCAN_B - 1) / SCAN_B)   // 98

// ---- scratch (device globals; no allocation allowed) ----
__device__ __align__(16) float g_self[NF];
__device__ __align__(16) float g_bsum[NF];
__device__ __align__(16) float g_esum[NF];
__device__ __align__(16) float g_bmax[NF];
__device__ __align__(16) float g_emax[NF];
__device__ __align__(16) float g_segmax[NF];
__device__ __align__(16) float g_sumagg[NF];

__device__ int d_deg[NN];
__device__ int d_row[NN + 1];
__device__ int d_cur[NN];
__device__ int d_bsumI[NBLK];
__device__ int d_boff[NBLK];
__device__ int d_ei[NE];          // end ids sorted by begin id

// B pre-packed in MMA fragment lane order, tf32-converted.
__device__ __align__(16) float d_B2[5 * 8 * 2 * 8 * 32 * 2];

__device__ __align__(16) float d_sum_s[64];
__device__ __align__(16) float d_ss_s[64];
__device__ __align__(16) float d_mu_s[64];
__device__ __align__(16) float d_istd_s[64];
__device__ __align__(16) float d_sum_g[128];
__device__ __align__(16) float d_ss_g[128];
__device__ __align__(16) float d_a_g[128];
__device__ __align__(16) float d_c_g[128];
__device__ __align__(16) float d_Wp[128 * 64];
__device__ __align__(16) float d_doff[64];
__device__ int   d_min_i;

// ---- monotone float<->int key ----
__device__ __forceinline__ int fkey(float f) {
    int i = __float_as_int(f);
    return i >= 0 ? i : (i ^ 0x7fffffff);
}
__device__ __forceinline__ float fdec(int k) {
    return __int_as_float(k >= 0 ? k : (k ^ 0x7fffffff));
}

// tf32 cvt: PTX requires .b32 destination register
__device__ __forceinline__ float to_tf32(float v) {
    unsigned r;
    asm("cvt.rna.tf32.f32 %0, %1;" : "=r"(r) : "f"(v));
    return __uint_as_float(r);
}
__device__ __forceinline__ float4 to_tf32_4(float4 v) {
    float4 r;
    r.x = to_tf32(v.x); r.y = to_tf32(v.y);
    r.z = to_tf32(v.z); r.w = to_tf32(v.w);
    return r;
}

// ---- K0: init small scratch ----
__global__ void k_init() {
    int i = blockIdx.x * blockDim.x + threadIdx.x;
    int stride = gridDim.x * blockDim.x;
    for (int j = i; j < NN; j += stride) d_deg[j] = 0;
    if (i < 64)  { d_sum_s[i] = 0.0f; d_ss_s[i] = 0.0f; }
    if (i < 128) { d_sum_g[i] = 0.0f; d_ss_g[i] = 0.0f; }
    if (i == 0)  d_min_i = INT_MAX;
}

// ---- CSR build ----
__global__ void k_deg(const int* __restrict__ b) {
    int i = blockIdx.x * blockDim.x + threadIdx.x;
    int stride = gridDim.x * blockDim.x;
    for (; i < NE; i += stride) atomicAdd(&d_deg[b[i]], 1);
}

// ---- pre-pack B into fragment lane order (tf32) ----
__global__ void k_prepB(const float* __restrict__ B) {  // [128,320]
    int idx = blockIdx.x * blockDim.x + threadIdx.x;    // 0..40959
    if (idx >= 5 * 8 * 2 * 8 * 32) return;
    int lane = idx & 31;
    int t = idx >> 5;
    int nbk = t & 7;  t >>= 3;
    int ks  = t & 1;  t >>= 1;
    int kc  = t & 7;  t >>= 3;
    int slice = t;                      // 0..4
    int g = lane >> 2, tig = lane & 3;
    int k = kc * 16 + ks * 8 + tig;
    int n = slice * 64 + nbk * 8 + g;
    float2 v;
    v.x = to_tf32(B[k * 320 + n]);
    v.y = to_tf32(B[(k + 4) * 320 + n]);
    *(float2*)&d_B2[idx * 2] = v;
}

__global__ void k_scan1() {
    __shared__ int sh[SCAN_B];
    int i = blockIdx.x * SCAN_B + threadIdx.x;
    sh[threadIdx.x] = (i < NN) ? d_deg[i] : 0;
    __syncthreads();
    for (int off = SCAN_B / 2; off; off >>= 1) {
        if (threadIdx.x < off) sh[threadIdx.x] += sh[threadIdx.x + off];
        __syncthreads();
    }
    if (threadIdx.x == 0) d_bsumI[blockIdx.x] = sh[0];
}

__global__ void k_scan2() {
    int t = threadIdx.x;
    int v = (t < NBLK) ? d_bsumI[t] : 0;
    int x = v;
    #pragma unroll
    for (int off = 1; off < 32; off <<= 1) {
        int y = __shfl_up_sync(0xffffffffu, x, off);
        if ((t & 31) >= off) x += y;
    }
    __shared__ int wt[4];
    if ((t & 31) == 31) wt[t >> 5] = x;
    __syncthreads();
    int add = 0;
    for (int w = 0; w < (t >> 5); w++) add += wt[w];
    x += add;
    if (t < NBLK) d_boff[t] = x - v;
    if (t == 0) d_row[NN] = NE;
}

__global__ void k_scan3() {
    int t = threadIdx.x;
    int lane = t & 31, w = t >> 5;
    int i = blockIdx.x * SCAN_B + t;
    int v = (i < NN) ? d_deg[i] : 0;
    int x = v;
    #pragma unroll
    for (int off = 1; off < 32; off <<= 1) {
        int y = __shfl_up_sync(0xffffffffu, x, off);
        if (lane >= off) x += y;
    }
    __shared__ int wt[16];
    if (lane == 31) wt[w] = x;
    __syncthreads();
    int add = d_boff[blockIdx.x];
    for (int k = 0; k < w; k++) add += wt[k];
    int excl = x - v + add;
    if (i < NN) { d_row[i] = excl; d_cur[i] = excl; }
}

__global__ void k_fill(const int* __restrict__ b, const int* __restrict__ e) {
    int i = blockIdx.x * blockDim.x + threadIdx.x;
    int stride = gridDim.x * blockDim.x;
    for (; i < NE; i += stride) {
        int pos = atomicAdd(&d_cur[b[i]], 1);
        d_ei[pos] = e[i];
    }
}

// ---- K1: GEMM1 tf32 mma.sync, A double-buffered in smem, B from d_B2 (L2) ----
__global__ void __launch_bounds__(256, 2)
k_gemm1(const float* __restrict__ A,    // [NN,128]
        const float* __restrict__ bias) // [320]
{
    __shared__ __align__(16) float As[2][256][20];
    int tid = threadIdx.x;
    int lane = tid & 31, wid = tid >> 5;
    int wm = wid & 3, wn = wid >> 2;
    int g = lane >> 2, tig = lane & 3;
    int m0 = blockIdx.x * 256;
    int nb = blockIdx.y;

    float c[4][4][4];
    #pragma unroll
    for (int mt = 0; mt < 4; mt++)
        #pragma unroll
        for (int nt = 0; nt < 4; nt++)
            #pragma unroll
            for (int i = 0; i < 4; i++) c[mt][nt][i] = 0.0f;

    int frow = tid >> 2;
    int fc = (tid & 3) * 4;

    #pragma unroll
    for (int p = 0; p < 4; p++) {
        int row = p * 64 + frow;
        int gm = m0 + row;
        float4 v = make_float4(0.f, 0.f, 0.f, 0.f);
        if (gm < NN) v = *(const float4*)&A[gm * KIN + fc];
        *(float4*)&As[0][row][fc] = to_tf32_4(v);
    }
    __syncthreads();

    const float* b2base = &d_B2[(nb * 8) * 2 * 8 * 64];

    #pragma unroll
    for (int kci = 0; kci < 8; kci++) {
        int cur = kci & 1;
        float4 pf[4];
        if (kci < 7) {
            int kc = (kci + 1) * 16;
            #pragma unroll
            for (int p = 0; p < 4; p++) {
                int gm = m0 + p * 64 + frow;
                pf[p] = make_float4(0.f, 0.f, 0.f, 0.f);
                if (gm < NN) pf[p] = *(const float4*)&A[gm * KIN + kc + fc];
            }
        }

        #pragma unroll
        for (int ks = 0; ks < 2; ks++) {
            int kk = ks * 8 + tig;
            unsigned af[4][4];
            #pragma unroll
            for (int mt = 0; mt < 4; mt++) {
                int mr = wm * 64 + mt * 16;
                af[mt][0] = __float_as_uint(As[cur][mr + g][kk]);
                af[mt][1] = __float_as_uint(As[cur][mr + g + 8][kk]);
                af[mt][2] = __float_as_uint(As[cur][mr + g][kk + 4]);
                af[mt][3] = __float_as_uint(As[cur][mr + g + 8][kk + 4]);
            }
            #pragma unroll
            for (int nt = 0; nt < 4; nt++) {
                int nbk = wn * 4 + nt;
                float2 bf = *(const float2*)&b2base[(((kci * 2) + ks) * 8 + nbk) * 64 + lane * 2];
                unsigned b0 = __float_as_uint(bf.x);
                unsigned b1 = __float_as_uint(bf.y);
                #pragma unroll
                for (int mt = 0; mt < 4; mt++) {
                    asm volatile(
                        "mma.sync.aligned.m16n8k8.row.col.f32.tf32.tf32.f32 "
                        "{%0,%1,%2,%3}, {%4,%5,%6,%7}, {%8,%9}, {%0,%1,%2,%3};"
                        : "+f"(c[mt][nt][0]), "+f"(c[mt][nt][1]),
                          "+f"(c[mt][nt][2]), "+f"(c[mt][nt][3])
                        : "r"(af[mt][0]), "r"(af[mt][1]), "r"(af[mt][2]), "r"(af[mt][3]),
                          "r"(b0), "r"(b1));
                }
            }
        }

        if (kci < 7) {
            #pragma unroll
            for (int p = 0; p < 4; p++)
                *(float4*)&As[cur ^ 1][p * 64 + frow][fc] = to_tf32_4(pf[p]);
        }
        __syncthreads();
    }

    int n0 = nb * 64;
    float* outp = (nb == 0) ? g_self : (nb == 1) ? g_bsum :
                  (nb == 2) ? g_esum : (nb == 3) ? g_bmax : g_emax;
    #pragma unroll
    for (int mt = 0; mt < 4; mt++) {
        #pragma unroll
        for (int nt = 0; nt < 4; nt++) {
            int col = wn * 32 + nt * 8 + tig * 2;
            float bx = bias[n0 + col], by = bias[n0 + col + 1];
            int r0 = m0 + wm * 64 + mt * 16 + g;
            if (r0 < NN) {
                float2 o; o.x = c[mt][nt][0] + bx; o.y = c[mt][nt][1] + by;
                *(float2*)&outp[r0 * 64 + col] = o;
            }
            int r1 = r0 + 8;
            if (r1 < NN) {
                float2 o; o.x = c[mt][nt][2] + bx; o.y = c[mt][nt][3] + by;
                *(float2*)&outp[r1 * 64 + col] = o;
            }
        }
    }
}

// ---- pass A (round-6 version): per-node segment max + edge-BN stats + global min ----
__global__ void k_edgeA() {
    __shared__ float s_acc[128];
    __shared__ int s_min;
    int tid = threadIdx.x;
    int lane = tid & 31;
    if (tid < 128) s_acc[tid] = 0.0f;
    if (tid == 0) s_min = INT_MAX;
    __syncthreads();

    int warp = (blockIdx.x * blockDim.x + tid) >> 5;
    int nwarp = (gridDim.x * blockDim.x) >> 5;
    float asx = 0.f, asy = 0.f, aqx = 0.f, aqy = 0.f;
    float lmin = INFINITY;

    for (int n = warp; n < NN; n += nwarp) {
        int beg = d_row[n], end = d_row[n + 1];
        float2 bs = *(const float2*)&g_bsum[n * 64 + 2 * lane];
        float2 bm = *(const float2*)&g_bmax[n * 64 + 2 * lane];
        float mx = -INFINITY, my = -INFINITY;
        int e = beg;
        for (; e + 1 < end; e += 2) {
            int ei0 = d_ei[e], ei1 = d_ei[e + 1];
            float2 es0 = *(const float2*)&g_esum[ei0 * 64 + 2 * lane];
            float2 em0 = *(const float2*)&g_emax[ei0 * 64 + 2 * lane];
            float2 es1 = *(const float2*)&g_esum[ei1 * 64 + 2 * lane];
            float2 em1 = *(const float2*)&g_emax[ei1 * 64 + 2 * lane];
            float sx0 = bs.x + es0.x, sy0 = bs.y + es0.y;
            float sx1 = bs.x + es1.x, sy1 = bs.y + es1.y;
            asx += sx0 + sx1; asy += sy0 + sy1;
            aqx += sx0 * sx0 + sx1 * sx1;
            aqy += sy0 * sy0 + sy1 * sy1;
            float m0x = bm.x + em0.x, m0y = bm.y + em0.y;
            float m1x = bm.x + em1.x, m1y = bm.y + em1.y;
            mx = fmaxf(mx, fmaxf(m0x, m1x));
            my = fmaxf(my, fmaxf(m0y, m1y));
            lmin = fminf(lmin, fminf(fminf(m0x, m0y), fminf(m1x, m1y)));
        }
        if (e < end) {
            int ei0 = d_ei[e];
            float2 es0 = *(const float2*)&g_esum[ei0 * 64 + 2 * lane];
            float2 em0 = *(const float2*)&g_emax[ei0 * 64 + 2 * lane];
            float sx0 = bs.x + es0.x, sy0 = bs.y + es0.y;
            asx += sx0; asy += sy0;
            aqx += sx0 * sx0; aqy += sy0 * sy0;
            float m0x = bm.x + em0.x, m0y = bm.y + em0.y;
            mx = fmaxf(mx, m0x);
            my = fmaxf(my, m0y);
            lmin = fminf(lmin, fminf(m0x, m0y));
        }
        float2 o; o.x = mx; o.y = my;
        *(float2*)&g_segmax[n * 64 + 2 * lane] = o;
    }

    atomicAdd(&s_acc[2 * lane], asx);
    atomicAdd(&s_acc[2 * lane + 1], asy);
    atomicAdd(&s_acc[64 + 2 * lane], aqx);
    atomicAdd(&s_acc[64 + 2 * lane + 1], aqy);
    #pragma unroll
    for (int off = 16; off; off >>= 1)
        lmin = fminf(lmin, __shfl_xor_sync(0xffffffffu, lmin, off));
    if (lane == 0) atomicMin(&s_min, fkey(lmin));
    __syncthreads();
    if (tid < 64) {
        atomicAdd(&d_sum_s[tid], s_acc[tid]);
        atomicAdd(&d_ss_s[tid], s_acc[64 + tid]);
    }
    if (tid == 0) atomicMin(&d_min_i, s_min);
}

__global__ void k_fin_s() {
    int t = threadIdx.x;  // 64
    float mu = d_sum_s[t] / (float)NE;
    float var = d_ss_s[t] / (float)NE - mu * mu;
    d_mu_s[t] = mu;
    d_istd_s[t] = rsqrtf(var + 1e-5f);
}

// ---- pass B (round-6 version): per-node relu(bn(ef_sum)) sum + node-BN stats ----
__global__ void k_edgeB(const float* __restrict__ gamma,
                        const float* __restrict__ beta) {
    __shared__ float s_acc[128];
    int tid = threadIdx.x;
    int lane = tid & 31;
    if (tid < 128) s_acc[tid] = 0.0f;
    __syncthreads();

    int f0 = 2 * lane, f1 = 2 * lane + 1;
    float ax = d_istd_s[f0] * gamma[f0], ay = d_istd_s[f1] * gamma[f1];
    float cx = beta[f0] - d_mu_s[f0] * ax, cy = beta[f1] - d_mu_s[f1] * ay;

    int warp = (blockIdx.x * blockDim.x + tid) >> 5;
    int nwarp = (gridDim.x * blockDim.x) >> 5;
    float nsx = 0.f, nsy = 0.f, nqx = 0.f, nqy = 0.f;

    for (int n = warp; n < NN; n += nwarp) {
        int beg = d_row[n], end = d_row[n + 1];
        float2 bs = *(const float2*)&g_bsum[n * 64 + f0];
        float accx = 0.f, accy = 0.f;
        int e = beg;
        for (; e + 1 < end; e += 2) {
            int ei0 = d_ei[e], ei1 = d_ei[e + 1];
            float2 es0 = *(const float2*)&g_esum[ei0 * 64 + f0];
            float2 es1 = *(const float2*)&g_esum[ei1 * 64 + f0];
            accx += fmaxf(0.f, fmaf(bs.x + es0.x, ax, cx))
                  + fmaxf(0.f, fmaf(bs.x + es1.x, ax, cx));
            accy += fmaxf(0.f, fmaf(bs.y + es0.y, ay, cy))
                  + fmaxf(0.f, fmaf(bs.y + es1.y, ay, cy));
        }
        if (e < end) {
            int ei0 = d_ei[e];
            float2 es0 = *(const float2*)&g_esum[ei0 * 64 + f0];
            accx += fmaxf(0.f, fmaf(bs.x + es0.x, ax, cx));
            accy += fmaxf(0.f, fmaf(bs.y + es0.y, ay, cy));
        }
        float2 o; o.x = accx; o.y = accy;
        *(float2*)&g_sumagg[n * 64 + f0] = o;
        nsx += accx; nsy += accy;
        nqx += accx * accx; nqy += accy * accy;
    }

    atomicAdd(&s_acc[f0], nsx);
    atomicAdd(&s_acc[f1], nsy);
    atomicAdd(&s_acc[64 + f0], nqx);
    atomicAdd(&s_acc[64 + f1], nqy);
    __syncthreads();
    if (tid < 64) {
        atomicAdd(&d_sum_g[64 + tid], s_acc[tid]);
        atomicAdd(&d_ss_g[64 + tid], s_acc[64 + tid]);
    }
}

// ---- K5: empty-segment fix + node-BN stats for segmax half ----
__global__ void k_node() {
    __shared__ float s_acc[128];
    int tid = threadIdx.x;
    int lane = tid & 31;
    if (tid < 128) s_acc[tid] = 0.0f;
    __syncthreads();

    int f0 = 2 * lane;
    float minv = fdec(d_min_i);
    int warp = (blockIdx.x * blockDim.x + tid) >> 5;
    int nwarp = (gridDim.x * blockDim.x) >> 5;
    float nsx = 0.f, nsy = 0.f, nqx = 0.f, nqy = 0.f;
    for (int n = warp; n < NN; n += nwarp) {
        float2 v = *(const float2*)&g_segmax[n * 64 + f0];
        if (v.x == -INFINITY) {
            v.x = minv; v.y = minv;
            *(float2*)&g_segmax[n * 64 + f0] = v;
        }
        nsx += v.x; nsy += v.y;
        nqx += v.x * v.x; nqy += v.y * v.y;
    }
    atomicAdd(&s_acc[f0], nsx);
    atomicAdd(&s_acc[f0 + 1], nsy);
    atomicAdd(&s_acc[64 + f0], nqx);
    atomicAdd(&s_acc[64 + f0 + 1], nqy);
    __syncthreads();
    if (tid < 64) {
        atomicAdd(&d_sum_g[tid], s_acc[tid]);
        atomicAdd(&d_ss_g[tid], s_acc[64 + tid]);
    }
}

__global__ void k_fin_g(const float* __restrict__ gamma_u,
                        const float* __restrict__ beta_u,
                        const float* __restrict__ W_u) {
    int t = threadIdx.x;  // 256
    if (t < 128) {
        float mu = d_sum_g[t] / (float)NN;
        float var = d_ss_g[t] / (float)NN - mu * mu;
        float a = rsqrtf(var + 1e-5f) * gamma_u[t];
        d_a_g[t] = a;
        d_c_g[t] = beta_u[t] - mu * a;
    }
    __syncthreads();
    for (int idx = t; idx < 128 * 64; idx += 256)
        d_Wp[idx] = d_a_g[idx >> 6] * W_u[idx];
    if (t < 64) {
        float acc = 0.f;
        for (int k = 0; k < 128; k++) acc += d_c_g[k] * W_u[k * 64 + t];
        d_doff[t] = acc;
    }
}

// ---- K7: out = self + relu(g_raw @ W' + doff) ----
__global__ void k_final(float* __restrict__ out) {
    __shared__ __align__(16) float Ws[128 * 64];
    __shared__ float Ds[64];
    __shared__ float Gs[8][2][128];
    int tid = threadIdx.x;
    int lane = tid & 31, w = tid >> 5;
    for (int i = tid; i < 128 * 64; i += 256) Ws[i] = d_Wp[i];
    if (tid < 64) Ds[tid] = d_doff[tid];
    __syncthreads();

    int pair = blockIdx.x * 8 + w;
    int pstride = gridDim.x * 8;
    for (int p = pair; p < NN / 2; p += pstride) {
        int nA = 2 * p, nB = 2 * p + 1;
        Gs[w][0][lane]      = g_segmax[nA * 64 + lane];
        Gs[w][0][lane + 32] = g_segmax[nA * 64 + lane + 32];
        Gs[w][0][64 + lane] = g_sumagg[nA * 64 + lane];
        Gs[w][0][96 + lane] = g_sumagg[nA * 64 + lane + 32];
        Gs[w][1][lane]      = g_segmax[nB * 64 + lane];
        Gs[w][1][lane + 32] = g_segmax[nB * 64 + lane + 32];
        Gs[w][1][64 + lane] = g_sumagg[nB * 64 + lane];
        Gs[w][1][96 + lane] = g_sumagg[nB * 64 + lane + 32];
        __syncwarp();
        float a0 = 0.f, a1 = 0.f, b0 = 0.f, b1 = 0.f;
        #pragma unroll 4
        for (int k = 0; k < 128; k++) {
            float ga = Gs[w][0][k], gb = Gs[w][1][k];
            float w0 = Ws[k * 64 + lane], w1 = Ws[k * 64 + lane + 32];
            a0 += ga * w0; a1 += ga * w1;
            b0 += gb * w0; b1 += gb * w1;
        }
        out[nA * 64 + lane]      = g_self[nA * 64 + lane]      + fmaxf(0.f, a0 + Ds[lane]);
        out[nA * 64 + lane + 32] = g_self[nA * 64 + lane + 32] + fmaxf(0.f, a1 + Ds[lane + 32]);
        out[nB * 64 + lane]      = g_self[nB * 64 + lane]      + fmaxf(0.f, b0 + Ds[lane]);
        out[nB * 64 + lane + 32] = g_self[nB * 64 + lane + 32] + fmaxf(0.f, b1 + Ds[lane + 32]);
        __syncwarp();
    }
}

extern "C" void kernel_launch(void* const* d_in, const int* in_sizes, int n_in,
                              void* d_out, int out_size) {
    const float* n_feat  = (const float*)d_in[0];
    const int*   eidx    = (const int*)d_in[1];
    const float* W_b     = (const float*)d_in[2];
    const float* b_b     = (const float*)d_in[3];
    const float* gamma_g = (const float*)d_in[4];
    const float* beta_g  = (const float*)d_in[5];
    const float* gamma_u = (const float*)d_in[6];
    const float* beta_u  = (const float*)d_in[7];
    const float* W_u     = (const float*)d_in[8];
    float* out           = (float*)d_out;

    const int* begin_ids = eidx;
    const int* end_ids   = eidx + NE;

    k_init<<<256, 256>>>();
    k_deg<<<1184, 256>>>(begin_ids);
    k_prepB<<<160, 256>>>(W_b);
    // gemm1 at launch index 3 (0-based): ncu capture slot
    dim3 g1((NN + 255) / 256, 5);
    k_gemm1<<<g1, 256>>>(n_feat, b_b);
    k_scan1<<<NBLK, SCAN_B>>>();
    k_scan2<<<1, 128>>>();
    k_scan3<<<NBLK, SCAN_B>>>();
    k_fill<<<1184, 256>>>(begin_ids, end_ids);
    k_edgeA<<<1184, 256>>>();
    k_fin_s<<<1, 64>>>();
    k_edgeB<<<1184, 256>>>(gamma_g, beta_g);
    k_node<<<1184, 256>>>();
    k_fin_g<<<1, 256>>>(gamma_u, beta_u, W_u);
    k_final<<<1184, 256>>>(out);
}

// round 9
// speedup vs baseline: 1.1921x; 1.0429x over previous
#include <cuda_runtime.h>
#include <math.h>

#define NN 50000
#define NE 800000
#define KIN 128
#define F 64
#define NF (NN*F)
#define SCAN_B 512
#define NBLK ((NN + SCAN_B - 1) / SCAN_B)   // 98

// ---- scratch (device globals; no allocation allowed) ----
__device__ __align__(16) float g_self[NF];
__device__ __align__(16) float g_bsum[NF];
__device__ __align__(16) float g_esum[NF];
__device__ __align__(16) float g_bmax[NF];
__device__ __align__(16) float g_emax[NF];
__device__ __align__(16) float g_segmax[NF];
__device__ __align__(16) float g_sumagg[NF];

__device__ int d_deg[NN];
__device__ int d_row[NN + 1];
__device__ int d_cur[NN];
__device__ int d_bsumI[NBLK];
__device__ int d_boff[NBLK];
__device__ int d_ei[NE];          // end ids sorted by begin id

// B pre-packed in MMA fragment lane order, tf32-converted.
__device__ __align__(16) float d_B2[5 * 8 * 2 * 8 * 32 * 2];

__device__ __align__(16) float d_sum_s[64];
__device__ __align__(16) float d_ss_s[64];
__device__ __align__(16) float d_mu_s[64];
__device__ __align__(16) float d_istd_s[64];
__device__ __align__(16) float d_sum_g[128];
__device__ __align__(16) float d_ss_g[128];
__device__ __align__(16) float d_a_g[128];
__device__ __align__(16) float d_c_g[128];
__device__ __align__(16) float d_Wp[128 * 64];
__device__ __align__(16) float d_doff[64];
__device__ int   d_min_i;

// ---- monotone float<->int key ----
__device__ __forceinline__ int fkey(float f) {
    int i = __float_as_int(f);
    return i >= 0 ? i : (i ^ 0x7fffffff);
}
__device__ __forceinline__ float fdec(int k) {
    return __int_as_float(k >= 0 ? k : (k ^ 0x7fffffff));
}

// tf32 cvt: PTX requires .b32 destination register
__device__ __forceinline__ float to_tf32(float v) {
    unsigned r;
    asm("cvt.rna.tf32.f32 %0, %1;" : "=r"(r) : "f"(v));
    return __uint_as_float(r);
}
__device__ __forceinline__ float4 to_tf32_4(float4 v) {
    float4 r;
    r.x = to_tf32(v.x); r.y = to_tf32(v.y);
    r.z = to_tf32(v.z); r.w = to_tf32(v.w);
    return r;
}

// ---- K0: init small scratch ----
__global__ void k_init() {
    int i = blockIdx.x * blockDim.x + threadIdx.x;
    int stride = gridDim.x * blockDim.x;
    for (int j = i; j < NN; j += stride) d_deg[j] = 0;
    if (i < 64)  { d_sum_s[i] = 0.0f; d_ss_s[i] = 0.0f; }
    if (i < 128) { d_sum_g[i] = 0.0f; d_ss_g[i] = 0.0f; }
    if (i == 0)  d_min_i = INT_MAX;
}

// ---- CSR build ----
__global__ void k_deg(const int* __restrict__ b) {
    int i = blockIdx.x * blockDim.x + threadIdx.x;
    int stride = gridDim.x * blockDim.x;
    for (; i < NE; i += stride) atomicAdd(&d_deg[b[i]], 1);
}

// ---- pre-pack B into fragment lane order (tf32) ----
__global__ void k_prepB(const float* __restrict__ B) {  // [128,320]
    int idx = blockIdx.x * blockDim.x + threadIdx.x;    // 0..40959
    if (idx >= 5 * 8 * 2 * 8 * 32) return;
    int lane = idx & 31;
    int t = idx >> 5;
    int nbk = t & 7;  t >>= 3;
    int ks  = t & 1;  t >>= 1;
    int kc  = t & 7;  t >>= 3;
    int slice = t;                      // 0..4
    int g = lane >> 2, tig = lane & 3;
    int k = kc * 16 + ks * 8 + tig;
    int n = slice * 64 + nbk * 8 + g;
    float2 v;
    v.x = to_tf32(B[k * 320 + n]);
    v.y = to_tf32(B[(k + 4) * 320 + n]);
    *(float2*)&d_B2[idx * 2] = v;
}

__global__ void k_scan1() {
    __shared__ int sh[SCAN_B];
    int i = blockIdx.x * SCAN_B + threadIdx.x;
    sh[threadIdx.x] = (i < NN) ? d_deg[i] : 0;
    __syncthreads();
    for (int off = SCAN_B / 2; off; off >>= 1) {
        if (threadIdx.x < off) sh[threadIdx.x] += sh[threadIdx.x + off];
        __syncthreads();
    }
    if (threadIdx.x == 0) d_bsumI[blockIdx.x] = sh[0];
}

__global__ void k_scan2() {
    int t = threadIdx.x;
    int v = (t < NBLK) ? d_bsumI[t] : 0;
    int x = v;
    #pragma unroll
    for (int off = 1; off < 32; off <<= 1) {
        int y = __shfl_up_sync(0xffffffffu, x, off);
        if ((t & 31) >= off) x += y;
    }
    __shared__ int wt[4];
    if ((t & 31) == 31) wt[t >> 5] = x;
    __syncthreads();
    int add = 0;
    for (int w = 0; w < (t >> 5); w++) add += wt[w];
    x += add;
    if (t < NBLK) d_boff[t] = x - v;
    if (t == 0) d_row[NN] = NE;
}

__global__ void k_scan3() {
    int t = threadIdx.x;
    int lane = t & 31, w = t >> 5;
    int i = blockIdx.x * SCAN_B + t;
    int v = (i < NN) ? d_deg[i] : 0;
    int x = v;
    #pragma unroll
    for (int off = 1; off < 32; off <<= 1) {
        int y = __shfl_up_sync(0xffffffffu, x, off);
        if (lane >= off) x += y;
    }
    __shared__ int wt[16];
    if (lane == 31) wt[w] = x;
    __syncthreads();
    int add = d_boff[blockIdx.x];
    for (int k = 0; k < w; k++) add += wt[k];
    int excl = x - v + add;
    if (i < NN) { d_row[i] = excl; d_cur[i] = excl; }
}

__global__ void k_fill(const int* __restrict__ b, const int* __restrict__ e) {
    int i = blockIdx.x * blockDim.x + threadIdx.x;
    int stride = gridDim.x * blockDim.x;
    for (; i < NE; i += stride) {
        int pos = atomicAdd(&d_cur[b[i]], 1);
        d_ei[pos] = e[i];
    }
}

// ---- K1: GEMM1 tf32 mma.sync, A double-buffered in smem, B from d_B2 (L2) ----
__global__ void __launch_bounds__(256, 2)
k_gemm1(const float* __restrict__ A,    // [NN,128]
        const float* __restrict__ bias) // [320]
{
    __shared__ __align__(16) float As[2][256][20];
    int tid = threadIdx.x;
    int lane = tid & 31, wid = tid >> 5;
    int wm = wid & 3, wn = wid >> 2;
    int g = lane >> 2, tig = lane & 3;
    int m0 = blockIdx.x * 256;
    int nb = blockIdx.y;

    float c[4][4][4];
    #pragma unroll
    for (int mt = 0; mt < 4; mt++)
        #pragma unroll
        for (int nt = 0; nt < 4; nt++)
            #pragma unroll
            for (int i = 0; i < 4; i++) c[mt][nt][i] = 0.0f;

    int frow = tid >> 2;
    int fc = (tid & 3) * 4;

    #pragma unroll
    for (int p = 0; p < 4; p++) {
        int row = p * 64 + frow;
        int gm = m0 + row;
        float4 v = make_float4(0.f, 0.f, 0.f, 0.f);
        if (gm < NN) v = *(const float4*)&A[gm * KIN + fc];
        *(float4*)&As[0][row][fc] = to_tf32_4(v);
    }
    __syncthreads();

    const float* b2base = &d_B2[(nb * 8) * 2 * 8 * 64];

    #pragma unroll
    for (int kci = 0; kci < 8; kci++) {
        int cur = kci & 1;
        float4 pf[4];
        if (kci < 7) {
            int kc = (kci + 1) * 16;
            #pragma unroll
            for (int p = 0; p < 4; p++) {
                int gm = m0 + p * 64 + frow;
                pf[p] = make_float4(0.f, 0.f, 0.f, 0.f);
                if (gm < NN) pf[p] = *(const float4*)&A[gm * KIN + kc + fc];
            }
        }

        #pragma unroll
        for (int ks = 0; ks < 2; ks++) {
            int kk = ks * 8 + tig;
            unsigned af[4][4];
            #pragma unroll
            for (int mt = 0; mt < 4; mt++) {
                int mr = wm * 64 + mt * 16;
                af[mt][0] = __float_as_uint(As[cur][mr + g][kk]);
                af[mt][1] = __float_as_uint(As[cur][mr + g + 8][kk]);
                af[mt][2] = __float_as_uint(As[cur][mr + g][kk + 4]);
                af[mt][3] = __float_as_uint(As[cur][mr + g + 8][kk + 4]);
            }
            #pragma unroll
            for (int nt = 0; nt < 4; nt++) {
                int nbk = wn * 4 + nt;
                float2 bf = *(const float2*)&b2base[(((kci * 2) + ks) * 8 + nbk) * 64 + lane * 2];
                unsigned b0 = __float_as_uint(bf.x);
                unsigned b1 = __float_as_uint(bf.y);
                #pragma unroll
                for (int mt = 0; mt < 4; mt++) {
                    asm volatile(
                        "mma.sync.aligned.m16n8k8.row.col.f32.tf32.tf32.f32 "
                        "{%0,%1,%2,%3}, {%4,%5,%6,%7}, {%8,%9}, {%0,%1,%2,%3};"
                        : "+f"(c[mt][nt][0]), "+f"(c[mt][nt][1]),
                          "+f"(c[mt][nt][2]), "+f"(c[mt][nt][3])
                        : "r"(af[mt][0]), "r"(af[mt][1]), "r"(af[mt][2]), "r"(af[mt][3]),
                          "r"(b0), "r"(b1));
                }
            }
        }

        if (kci < 7) {
            #pragma unroll
            for (int p = 0; p < 4; p++)
                *(float4*)&As[cur ^ 1][p * 64 + frow][fc] = to_tf32_4(pf[p]);
        }
        __syncthreads();
    }

    int n0 = nb * 64;
    float* outp = (nb == 0) ? g_self : (nb == 1) ? g_bsum :
                  (nb == 2) ? g_esum : (nb == 3) ? g_bmax : g_emax;
    #pragma unroll
    for (int mt = 0; mt < 4; mt++) {
        #pragma unroll
        for (int nt = 0; nt < 4; nt++) {
            int col = wn * 32 + nt * 8 + tig * 2;
            float bx = bias[n0 + col], by = bias[n0 + col + 1];
            int r0 = m0 + wm * 64 + mt * 16 + g;
            if (r0 < NN) {
                float2 o; o.x = c[mt][nt][0] + bx; o.y = c[mt][nt][1] + by;
                *(float2*)&outp[r0 * 64 + col] = o;
            }
            int r1 = r0 + 8;
            if (r1 < NN) {
                float2 o; o.x = c[mt][nt][2] + bx; o.y = c[mt][nt][3] + by;
                *(float2*)&outp[r1 * 64 + col] = o;
            }
        }
    }
}

// ---- pass A: per-node segment max + edge-BN stats + global min ----
__global__ void k_edgeA() {
    __shared__ float s_acc[128];
    __shared__ int s_min;
    int tid = threadIdx.x;
    int lane = tid & 31;
    if (tid < 128) s_acc[tid] = 0.0f;
    if (tid == 0) s_min = INT_MAX;
    __syncthreads();

    int warp = (blockIdx.x * blockDim.x + tid) >> 5;
    int nwarp = (gridDim.x * blockDim.x) >> 5;
    float asx = 0.f, asy = 0.f, aqx = 0.f, aqy = 0.f;
    float lmin = INFINITY;

    for (int n = warp; n < NN; n += nwarp) {
        int beg = d_row[n], end = d_row[n + 1];
        float2 bs = *(const float2*)&g_bsum[n * 64 + 2 * lane];
        float2 bm = *(const float2*)&g_bmax[n * 64 + 2 * lane];
        float mx = -INFINITY, my = -INFINITY;
        int e = beg;
        for (; e + 1 < end; e += 2) {
            int ei0 = d_ei[e], ei1 = d_ei[e + 1];
            float2 es0 = *(const float2*)&g_esum[ei0 * 64 + 2 * lane];
            float2 em0 = *(const float2*)&g_emax[ei0 * 64 + 2 * lane];
            float2 es1 = *(const float2*)&g_esum[ei1 * 64 + 2 * lane];
            float2 em1 = *(const float2*)&g_emax[ei1 * 64 + 2 * lane];
            float sx0 = bs.x + es0.x, sy0 = bs.y + es0.y;
            float sx1 = bs.x + es1.x, sy1 = bs.y + es1.y;
            asx += sx0 + sx1; asy += sy0 + sy1;
            aqx += sx0 * sx0 + sx1 * sx1;
            aqy += sy0 * sy0 + sy1 * sy1;
            float m0x = bm.x + em0.x, m0y = bm.y + em0.y;
            float m1x = bm.x + em1.x, m1y = bm.y + em1.y;
            mx = fmaxf(mx, fmaxf(m0x, m1x));
            my = fmaxf(my, fmaxf(m0y, m1y));
            lmin = fminf(lmin, fminf(fminf(m0x, m0y), fminf(m1x, m1y)));
        }
        if (e < end) {
            int ei0 = d_ei[e];
            float2 es0 = *(const float2*)&g_esum[ei0 * 64 + 2 * lane];
            float2 em0 = *(const float2*)&g_emax[ei0 * 64 + 2 * lane];
            float sx0 = bs.x + es0.x, sy0 = bs.y + es0.y;
            asx += sx0; asy += sy0;
            aqx += sx0 * sx0; aqy += sy0 * sy0;
            float m0x = bm.x + em0.x, m0y = bm.y + em0.y;
            mx = fmaxf(mx, m0x);
            my = fmaxf(my, m0y);
            lmin = fminf(lmin, fminf(m0x, m0y));
        }
        float2 o; o.x = mx; o.y = my;
        *(float2*)&g_segmax[n * 64 + 2 * lane] = o;
    }

    atomicAdd(&s_acc[2 * lane], asx);
    atomicAdd(&s_acc[2 * lane + 1], asy);
    atomicAdd(&s_acc[64 + 2 * lane], aqx);
    atomicAdd(&s_acc[64 + 2 * lane + 1], aqy);
    #pragma unroll
    for (int off = 16; off; off >>= 1)
        lmin = fminf(lmin, __shfl_xor_sync(0xffffffffu, lmin, off));
    if (lane == 0) atomicMin(&s_min, fkey(lmin));
    __syncthreads();
    if (tid < 64) {
        atomicAdd(&d_sum_s[tid], s_acc[tid]);
        atomicAdd(&d_ss_s[tid], s_acc[64 + tid]);
    }
    if (tid == 0) atomicMin(&d_min_i, s_min);
}

__global__ void k_fin_s() {
    int t = threadIdx.x;  // 64
    float mu = d_sum_s[t] / (float)NE;
    float var = d_ss_s[t] / (float)NE - mu * mu;
    d_mu_s[t] = mu;
    d_istd_s[t] = rsqrtf(var + 1e-5f);
}

// ---- pass B: per-node relu(bn(ef_sum)) sum + node-BN stats (sumagg half) ----
__global__ void k_edgeB(const float* __restrict__ gamma,
                        const float* __restrict__ beta) {
    __shared__ float s_acc[128];
    int tid = threadIdx.x;
    int lane = tid & 31;
    if (tid < 128) s_acc[tid] = 0.0f;
    __syncthreads();

    int f0 = 2 * lane, f1 = 2 * lane + 1;
    float ax = d_istd_s[f0] * gamma[f0], ay = d_istd_s[f1] * gamma[f1];
    float cx = beta[f0] - d_mu_s[f0] * ax, cy = beta[f1] - d_mu_s[f1] * ay;

    int warp = (blockIdx.x * blockDim.x + tid) >> 5;
    int nwarp = (gridDim.x * blockDim.x) >> 5;
    float nsx = 0.f, nsy = 0.f, nqx = 0.f, nqy = 0.f;

    for (int n = warp; n < NN; n += nwarp) {
        int beg = d_row[n], end = d_row[n + 1];
        float2 bs = *(const float2*)&g_bsum[n * 64 + f0];
        float accx = 0.f, accy = 0.f;
        int e = beg;
        for (; e + 1 < end; e += 2) {
            int ei0 = d_ei[e], ei1 = d_ei[e + 1];
            float2 es0 = *(const float2*)&g_esum[ei0 * 64 + f0];
            float2 es1 = *(const float2*)&g_esum[ei1 * 64 + f0];
            accx += fmaxf(0.f, fmaf(bs.x + es0.x, ax, cx))
                  + fmaxf(0.f, fmaf(bs.x + es1.x, ax, cx));
            accy += fmaxf(0.f, fmaf(bs.y + es0.y, ay, cy))
                  + fmaxf(0.f, fmaf(bs.y + es1.y, ay, cy));
        }
        if (e < end) {
            int ei0 = d_ei[e];
            float2 es0 = *(const float2*)&g_esum[ei0 * 64 + f0];
            accx += fmaxf(0.f, fmaf(bs.x + es0.x, ax, cx));
            accy += fmaxf(0.f, fmaf(bs.y + es0.y, ay, cy));
        }
        float2 o; o.x = accx; o.y = accy;
        *(float2*)&g_sumagg[n * 64 + f0] = o;
        nsx += accx; nsy += accy;
        nqx += accx * accx; nqy += accy * accy;
    }

    atomicAdd(&s_acc[f0], nsx);
    atomicAdd(&s_acc[f1], nsy);
    atomicAdd(&s_acc[64 + f0], nqx);
    atomicAdd(&s_acc[64 + f1], nqy);
    __syncthreads();
    if (tid < 64) {
        atomicAdd(&d_sum_g[64 + tid], s_acc[tid]);
        atomicAdd(&d_ss_g[64 + tid], s_acc[64 + tid]);
    }
}

// ---- K5: empty-segment fix + node-BN stats for segmax half ----
__global__ void k_node() {
    __shared__ float s_acc[128];
    int tid = threadIdx.x;
    int lane = tid & 31;
    if (tid < 128) s_acc[tid] = 0.0f;
    __syncthreads();

    int f0 = 2 * lane;
    float minv = fdec(d_min_i);
    int warp = (blockIdx.x * blockDim.x + tid) >> 5;
    int nwarp = (gridDim.x * blockDim.x) >> 5;
    float nsx = 0.f, nsy = 0.f, nqx = 0.f, nqy = 0.f;
    for (int n = warp; n < NN; n += nwarp) {
        float2 v = *(const float2*)&g_segmax[n * 64 + f0];
        if (v.x == -INFINITY) {
            v.x = minv; v.y = minv;
            *(float2*)&g_segmax[n * 64 + f0] = v;
        }
        nsx += v.x; nsy += v.y;
        nqx += v.x * v.x; nqy += v.y * v.y;
    }
    atomicAdd(&s_acc[f0], nsx);
    atomicAdd(&s_acc[f0 + 1], nsy);
    atomicAdd(&s_acc[64 + f0], nqx);
    atomicAdd(&s_acc[64 + f0 + 1], nqy);
    __syncthreads();
    if (tid < 64) {
        atomicAdd(&d_sum_g[tid], s_acc[tid]);
        atomicAdd(&d_ss_g[tid], s_acc[64 + tid]);
    }
}

__global__ void k_fin_g(const float* __restrict__ gamma_u,
                        const float* __restrict__ beta_u,
                        const float* __restrict__ W_u) {
    int t = threadIdx.x;  // 256
    if (t < 128) {
        float mu = d_sum_g[t] / (float)NN;
        float var = d_ss_g[t] / (float)NN - mu * mu;
        float a = rsqrtf(var + 1e-5f) * gamma_u[t];
        d_a_g[t] = a;
        d_c_g[t] = beta_u[t] - mu * a;
    }
    __syncthreads();
    for (int idx = t; idx < 128 * 64; idx += 256)
        d_Wp[idx] = d_a_g[idx >> 6] * W_u[idx];
    if (t < 64) {
        float acc = 0.f;
        for (int k = 0; k < 128; k++) acc += d_c_g[k] * W_u[k * 64 + t];
        d_doff[t] = acc;
    }
}

// ---- K7: out = self + relu(g_raw @ W' + doff) ----
__global__ void k_final(float* __restrict__ out) {
    __shared__ __align__(16) float Ws[128 * 64];
    __shared__ float Ds[64];
    __shared__ float Gs[8][2][128];
    int tid = threadIdx.x;
    int lane = tid & 31, w = tid >> 5;
    for (int i = tid; i < 128 * 64; i += 256) Ws[i] = d_Wp[i];
    if (tid < 64) Ds[tid] = d_doff[tid];
    __syncthreads();

    int pair = blockIdx.x * 8 + w;
    int pstride = gridDim.x * 8;
    for (int p = pair; p < NN / 2; p += pstride) {
        int nA = 2 * p, nB = 2 * p + 1;
        Gs[w][0][lane]      = g_segmax[nA * 64 + lane];
        Gs[w][0][lane + 32] = g_segmax[nA * 64 + lane + 32];
        Gs[w][0][64 + lane] = g_sumagg[nA * 64 + lane];
        Gs[w][0][96 + lane] = g_sumagg[nA * 64 + lane + 32];
        Gs[w][1][lane]      = g_segmax[nB * 64 + lane];
        Gs[w][1][lane + 32] = g_segmax[nB * 64 + lane + 32];
        Gs[w][1][64 + lane] = g_sumagg[nB * 64 + lane];
        Gs[w][1][96 + lane] = g_sumagg[nB * 64 + lane + 32];
        __syncwarp();
        float a0 = 0.f, a1 = 0.f, b0 = 0.f, b1 = 0.f;
        #pragma unroll 4
        for (int k = 0; k < 128; k++) {
            float ga = Gs[w][0][k], gb = Gs[w][1][k];
            float w0 = Ws[k * 64 + lane], w1 = Ws[k * 64 + lane + 32];
            a0 += ga * w0; a1 += ga * w1;
            b0 += gb * w0; b1 += gb * w1;
        }
        out[nA * 64 + lane]      = g_self[nA * 64 + lane]      + fmaxf(0.f, a0 + Ds[lane]);
        out[nA * 64 + lane + 32] = g_self[nA * 64 + lane + 32] + fmaxf(0.f, a1 + Ds[lane + 32]);
        out[nB * 64 + lane]      = g_self[nB * 64 + lane]      + fmaxf(0.f, b0 + Ds[lane]);
        out[nB * 64 + lane + 32] = g_self[nB * 64 + lane + 32] + fmaxf(0.f, b1 + Ds[lane + 32]);
        __syncwarp();
    }
}

extern "C" void kernel_launch(void* const* d_in, const int* in_sizes, int n_in,
                              void* d_out, int out_size) {
    const float* n_feat  = (const float*)d_in[0];
    const int*   eidx    = (const int*)d_in[1];
    const float* W_b     = (const float*)d_in[2];
    const float* b_b     = (const float*)d_in[3];
    const float* gamma_g = (const float*)d_in[4];
    const float* beta_g  = (const float*)d_in[5];
    const float* gamma_u = (const float*)d_in[6];
    const float* beta_u  = (const float*)d_in[7];
    const float* W_u     = (const float*)d_in[8];
    float* out           = (float*)d_out;

    const int* begin_ids = eidx;
    const int* end_ids   = eidx + NE;

    // lazily create side stream + events on first (uncaptured) call
    static cudaStream_t s1 = 0;
    static cudaEvent_t evFork = 0, evJoin = 0, evFork2 = 0, evJoin2 = 0;
    if (!s1) {
        cudaStreamCreateWithFlags(&s1, cudaStreamNonBlocking);
        cudaEventCreateWithFlags(&evFork, cudaEventDisableTiming);
        cudaEventCreateWithFlags(&evJoin, cudaEventDisableTiming);
        cudaEventCreateWithFlags(&evFork2, cudaEventDisableTiming);
        cudaEventCreateWithFlags(&evJoin2, cudaEventDisableTiming);
    }

    // fork: GEMM chain on s1, CSR chain on default stream — independent
    cudaEventRecord(evFork, 0);
    cudaStreamWaitEvent(s1, evFork, 0);
    k_prepB<<<160, 256, 0, s1>>>(W_b);
    dim3 g1((NN + 255) / 256, 5);
    k_gemm1<<<g1, 256, 0, s1>>>(n_feat, b_b);

    k_init<<<256, 256>>>();
    k_deg<<<1184, 256>>>(begin_ids);
    k_scan1<<<NBLK, SCAN_B>>>();
    k_scan2<<<1, 128>>>();
    k_scan3<<<NBLK, SCAN_B>>>();
    k_fill<<<1184, 256>>>(begin_ids, end_ids);

    // join: edgeA needs both GEMM outputs and CSR
    cudaEventRecord(evJoin, s1);
    cudaStreamWaitEvent(0, evJoin, 0);
    k_edgeA<<<1184, 256>>>();

    // fork 2: k_node (needs only edgeA) overlaps fin_s+edgeB (disjoint d_sum_g halves)
    cudaEventRecord(evFork2, 0);
    cudaStreamWaitEvent(s1, evFork2, 0);
    k_node<<<1184, 256, 0, s1>>>();

    k_fin_s<<<1, 64>>>();
    k_edgeB<<<1184, 256>>>(gamma_g, beta_g);

    cudaEventRecord(evJoin2, s1);
    cudaStreamWaitEvent(0, evJoin2, 0);
    k_fin_g<<<1, 256>>>(gamma_u, beta_u, W_u);
    k_final<<<1184, 256>>>(out);
}

// round 10
// speedup vs baseline: 1.4374x; 1.2058x over previous
#include <cuda_runtime.h>
#include <math.h>

#define NN 50000
#define NE 800000
#define KIN 128
#define F 64
#define NF (NN*F)
#define SCAN_B 512
#define NBLK ((NN + SCAN_B - 1) / SCAN_B)   // 98

// ---- scratch (device globals; no allocation allowed) ----
__device__ __align__(16) float g_self[NF];
__device__ __align__(16) float g_bsum[NF];
__device__ __align__(16) float g_esum[NF];
__device__ __align__(16) float g_bmax[NF];
__device__ __align__(16) float g_emax[NF];
__device__ __align__(16) float g_segmax[NF];
__device__ __align__(16) float g_sumagg[NF];

__device__ int d_deg[NN];
__device__ int d_row[NN + 1];
__device__ int d_cur[NN];
__device__ int d_bsumI[NBLK];
__device__ int d_boff[NBLK];
__device__ int d_ei[NE];          // end ids sorted by begin id

// B (W_b) pre-packed in MMA fragment lane order, tf32-converted.
__device__ __align__(16) float d_B2[5 * 8 * 2 * 8 * 32 * 2];
// BN-folded W_u pre-packed in fragment lane order (single 64-col slice).
__device__ __align__(16) float d_W2[8 * 2 * 8 * 32 * 2];

__device__ __align__(16) float d_sum_s[64];
__device__ __align__(16) float d_ss_s[64];
__device__ __align__(16) float d_sum_g[128];
__device__ __align__(16) float d_ss_g[128];
__device__ __align__(16) float d_a_g[128];
__device__ __align__(16) float d_c_g[128];
__device__ __align__(16) float d_doff[64];
__device__ int   d_min_i;

// ---- monotone float<->int key ----
__device__ __forceinline__ int fkey(float f) {
    int i = __float_as_int(f);
    return i >= 0 ? i : (i ^ 0x7fffffff);
}
__device__ __forceinline__ float fdec(int k) {
    return __int_as_float(k >= 0 ? k : (k ^ 0x7fffffff));
}

// tf32 cvt: PTX requires .b32 destination register
__device__ __forceinline__ float to_tf32(float v) {
    unsigned r;
    asm("cvt.rna.tf32.f32 %0, %1;" : "=r"(r) : "f"(v));
    return __uint_as_float(r);
}
__device__ __forceinline__ float4 to_tf32_4(float4 v) {
    float4 r;
    r.x = to_tf32(v.x); r.y = to_tf32(v.y);
    r.z = to_tf32(v.z); r.w = to_tf32(v.w);
    return r;
}

// ---- K0: init small scratch ----
__global__ void k_init() {
    int i = blockIdx.x * blockDim.x + threadIdx.x;
    int stride = gridDim.x * blockDim.x;
    for (int j = i; j < NN; j += stride) d_deg[j] = 0;
    if (i < 64)  { d_sum_s[i] = 0.0f; d_ss_s[i] = 0.0f; }
    if (i < 128) { d_sum_g[i] = 0.0f; d_ss_g[i] = 0.0f; }
    if (i == 0)  d_min_i = INT_MAX;
}

// ---- CSR build ----
__global__ void k_deg(const int* __restrict__ b) {
    int i = blockIdx.x * blockDim.x + threadIdx.x;
    int stride = gridDim.x * blockDim.x;
    for (; i < NE; i += stride) atomicAdd(&d_deg[b[i]], 1);
}

// ---- pre-pack B into fragment lane order (tf32) ----
__global__ void k_prepB(const float* __restrict__ B) {  // [128,320]
    int idx = blockIdx.x * blockDim.x + threadIdx.x;    // 0..40959
    if (idx >= 5 * 8 * 2 * 8 * 32) return;
    int lane = idx & 31;
    int t = idx >> 5;
    int nbk = t & 7;  t >>= 3;
    int ks  = t & 1;  t >>= 1;
    int kc  = t & 7;  t >>= 3;
    int slice = t;                      // 0..4
    int g = lane >> 2, tig = lane & 3;
    int k = kc * 16 + ks * 8 + tig;
    int n = slice * 64 + nbk * 8 + g;
    float2 v;
    v.x = to_tf32(B[k * 320 + n]);
    v.y = to_tf32(B[(k + 4) * 320 + n]);
    *(float2*)&d_B2[idx * 2] = v;
}

__global__ void k_scan1() {
    __shared__ int sh[SCAN_B];
    int i = blockIdx.x * SCAN_B + threadIdx.x;
    sh[threadIdx.x] = (i < NN) ? d_deg[i] : 0;
    __syncthreads();
    for (int off = SCAN_B / 2; off; off >>= 1) {
        if (threadIdx.x < off) sh[threadIdx.x] += sh[threadIdx.x + off];
        __syncthreads();
    }
    if (threadIdx.x == 0) d_bsumI[blockIdx.x] = sh[0];
}

__global__ void k_scan2() {
    int t = threadIdx.x;
    int v = (t < NBLK) ? d_bsumI[t] : 0;
    int x = v;
    #pragma unroll
    for (int off = 1; off < 32; off <<= 1) {
        int y = __shfl_up_sync(0xffffffffu, x, off);
        if ((t & 31) >= off) x += y;
    }
    __shared__ int wt[4];
    if ((t & 31) == 31) wt[t >> 5] = x;
    __syncthreads();
    int add = 0;
    for (int w = 0; w < (t >> 5); w++) add += wt[w];
    x += add;
    if (t < NBLK) d_boff[t] = x - v;
    if (t == 0) d_row[NN] = NE;
}

__global__ void k_scan3() {
    int t = threadIdx.x;
    int lane = t & 31, w = t >> 5;
    int i = blockIdx.x * SCAN_B + t;
    int v = (i < NN) ? d_deg[i] : 0;
    int x = v;
    #pragma unroll
    for (int off = 1; off < 32; off <<= 1) {
        int y = __shfl_up_sync(0xffffffffu, x, off);
        if (lane >= off) x += y;
    }
    __shared__ int wt[16];
    if (lane == 31) wt[w] = x;
    __syncthreads();
    int add = d_boff[blockIdx.x];
    for (int k = 0; k < w; k++) add += wt[k];
    int excl = x - v + add;
    if (i < NN) { d_row[i] = excl; d_cur[i] = excl; }
}

__global__ void k_fill(const int* __restrict__ b, const int* __restrict__ e) {
    int i = blockIdx.x * blockDim.x + threadIdx.x;
    int stride = gridDim.x * blockDim.x;
    for (; i < NE; i += stride) {
        int pos = atomicAdd(&d_cur[b[i]], 1);
        d_ei[pos] = e[i];
    }
}

// ---- K1: GEMM1 tf32 mma.sync, A double-buffered in smem, B from d_B2 (L2) ----
__global__ void __launch_bounds__(256, 2)
k_gemm1(const float* __restrict__ A,    // [NN,128]
        const float* __restrict__ bias) // [320]
{
    __shared__ __align__(16) float As[2][256][20];
    int tid = threadIdx.x;
    int lane = tid & 31, wid = tid >> 5;
    int wm = wid & 3, wn = wid >> 2;
    int g = lane >> 2, tig = lane & 3;
    int m0 = blockIdx.x * 256;
    int nb = blockIdx.y;

    float c[4][4][4];
    #pragma unroll
    for (int mt = 0; mt < 4; mt++)
        #pragma unroll
        for (int nt = 0; nt < 4; nt++)
            #pragma unroll
            for (int i = 0; i < 4; i++) c[mt][nt][i] = 0.0f;

    int frow = tid >> 2;
    int fc = (tid & 3) * 4;

    #pragma unroll
    for (int p = 0; p < 4; p++) {
        int row = p * 64 + frow;
        int gm = m0 + row;
        float4 v = make_float4(0.f, 0.f, 0.f, 0.f);
        if (gm < NN) v = *(const float4*)&A[gm * KIN + fc];
        *(float4*)&As[0][row][fc] = to_tf32_4(v);
    }
    __syncthreads();

    const float* b2base = &d_B2[(nb * 8) * 2 * 8 * 64];

    #pragma unroll
    for (int kci = 0; kci < 8; kci++) {
        int cur = kci & 1;
        float4 pf[4];
        if (kci < 7) {
            int kc = (kci + 1) * 16;
            #pragma unroll
            for (int p = 0; p < 4; p++) {
                int gm = m0 + p * 64 + frow;
                pf[p] = make_float4(0.f, 0.f, 0.f, 0.f);
                if (gm < NN) pf[p] = *(const float4*)&A[gm * KIN + kc + fc];
            }
        }

        #pragma unroll
        for (int ks = 0; ks < 2; ks++) {
            int kk = ks * 8 + tig;
            unsigned af[4][4];
            #pragma unroll
            for (int mt = 0; mt < 4; mt++) {
                int mr = wm * 64 + mt * 16;
                af[mt][0] = __float_as_uint(As[cur][mr + g][kk]);
                af[mt][1] = __float_as_uint(As[cur][mr + g + 8][kk]);
                af[mt][2] = __float_as_uint(As[cur][mr + g][kk + 4]);
                af[mt][3] = __float_as_uint(As[cur][mr + g + 8][kk + 4]);
            }
            #pragma unroll
            for (int nt = 0; nt < 4; nt++) {
                int nbk = wn * 4 + nt;
                float2 bf = *(const float2*)&b2base[(((kci * 2) + ks) * 8 + nbk) * 64 + lane * 2];
                unsigned b0 = __float_as_uint(bf.x);
                unsigned b1 = __float_as_uint(bf.y);
                #pragma unroll
                for (int mt = 0; mt < 4; mt++) {
                    asm volatile(
                        "mma.sync.aligned.m16n8k8.row.col.f32.tf32.tf32.f32 "
                        "{%0,%1,%2,%3}, {%4,%5,%6,%7}, {%8,%9}, {%0,%1,%2,%3};"
                        : "+f"(c[mt][nt][0]), "+f"(c[mt][nt][1]),
                          "+f"(c[mt][nt][2]), "+f"(c[mt][nt][3])
                        : "r"(af[mt][0]), "r"(af[mt][1]), "r"(af[mt][2]), "r"(af[mt][3]),
                          "r"(b0), "r"(b1));
                }
            }
        }

        if (kci < 7) {
            #pragma unroll
            for (int p = 0; p < 4; p++)
                *(float4*)&As[cur ^ 1][p * 64 + frow][fc] = to_tf32_4(pf[p]);
        }
        __syncthreads();
    }

    int n0 = nb * 64;
    float* outp = (nb == 0) ? g_self : (nb == 1) ? g_bsum :
                  (nb == 2) ? g_esum : (nb == 3) ? g_bmax : g_emax;
    #pragma unroll
    for (int mt = 0; mt < 4; mt++) {
        #pragma unroll
        for (int nt = 0; nt < 4; nt++) {
            int col = wn * 32 + nt * 8 + tig * 2;
            float bx = bias[n0 + col], by = bias[n0 + col + 1];
            int r0 = m0 + wm * 64 + mt * 16 + g;
            if (r0 < NN) {
                float2 o; o.x = c[mt][nt][0] + bx; o.y = c[mt][nt][1] + by;
                *(float2*)&outp[r0 * 64 + col] = o;
            }
            int r1 = r0 + 8;
            if (r1 < NN) {
                float2 o; o.x = c[mt][nt][2] + bx; o.y = c[mt][nt][3] + by;
                *(float2*)&outp[r1 * 64 + col] = o;
            }
        }
    }
}

// ---- pass A: per-node segment max + edge-BN stats + global min ----
__global__ void k_edgeA() {
    __shared__ float s_acc[128];
    __shared__ int s_min;
    int tid = threadIdx.x;
    int lane = tid & 31;
    if (tid < 128) s_acc[tid] = 0.0f;
    if (tid == 0) s_min = INT_MAX;
    __syncthreads();

    int warp = (blockIdx.x * blockDim.x + tid) >> 5;
    int nwarp = (gridDim.x * blockDim.x) >> 5;
    float asx = 0.f, asy = 0.f, aqx = 0.f, aqy = 0.f;
    float lmin = INFINITY;

    for (int n = warp; n < NN; n += nwarp) {
        int beg = d_row[n], end = d_row[n + 1];
        float2 bs = *(const float2*)&g_bsum[n * 64 + 2 * lane];
        float2 bm = *(const float2*)&g_bmax[n * 64 + 2 * lane];
        float mx = -INFINITY, my = -INFINITY;
        int e = beg;
        for (; e + 1 < end; e += 2) {
            int ei0 = d_ei[e], ei1 = d_ei[e + 1];
            float2 es0 = *(const float2*)&g_esum[ei0 * 64 + 2 * lane];
            float2 em0 = *(const float2*)&g_emax[ei0 * 64 + 2 * lane];
            float2 es1 = *(const float2*)&g_esum[ei1 * 64 + 2 * lane];
            float2 em1 = *(const float2*)&g_emax[ei1 * 64 + 2 * lane];
            float sx0 = bs.x + es0.x, sy0 = bs.y + es0.y;
            float sx1 = bs.x + es1.x, sy1 = bs.y + es1.y;
            asx += sx0 + sx1; asy += sy0 + sy1;
            aqx += sx0 * sx0 + sx1 * sx1;
            aqy += sy0 * sy0 + sy1 * sy1;
            float m0x = bm.x + em0.x, m0y = bm.y + em0.y;
            float m1x = bm.x + em1.x, m1y = bm.y + em1.y;
            mx = fmaxf(mx, fmaxf(m0x, m1x));
            my = fmaxf(my, fmaxf(m0y, m1y));
            lmin = fminf(lmin, fminf(fminf(m0x, m0y), fminf(m1x, m1y)));
        }
        if (e < end) {
            int ei0 = d_ei[e];
            float2 es0 = *(const float2*)&g_esum[ei0 * 64 + 2 * lane];
            float2 em0 = *(const float2*)&g_emax[ei0 * 64 + 2 * lane];
            float sx0 = bs.x + es0.x, sy0 = bs.y + es0.y;
            asx += sx0; asy += sy0;
            aqx += sx0 * sx0; aqy += sy0 * sy0;
            float m0x = bm.x + em0.x, m0y = bm.y + em0.y;
            mx = fmaxf(mx, m0x);
            my = fmaxf(my, m0y);
            lmin = fminf(lmin, fminf(m0x, m0y));
        }
        float2 o; o.x = mx; o.y = my;
        *(float2*)&g_segmax[n * 64 + 2 * lane] = o;
    }

    atomicAdd(&s_acc[2 * lane], asx);
    atomicAdd(&s_acc[2 * lane + 1], asy);
    atomicAdd(&s_acc[64 + 2 * lane], aqx);
    atomicAdd(&s_acc[64 + 2 * lane + 1], aqy);
    #pragma unroll
    for (int off = 16; off; off >>= 1)
        lmin = fminf(lmin, __shfl_xor_sync(0xffffffffu, lmin, off));
    if (lane == 0) atomicMin(&s_min, fkey(lmin));
    __syncthreads();
    if (tid < 64) {
        atomicAdd(&d_sum_s[tid], s_acc[tid]);
        atomicAdd(&d_ss_s[tid], s_acc[64 + tid]);
    }
    if (tid == 0) atomicMin(&d_min_i, s_min);
}

// ---- pass B: relu(bn(ef_sum)) per-node sum + node-BN stats (sumagg half) ----
// edge-BN stats finalized inline from raw sums (k_fin_s folded in)
__global__ void k_edgeB(const float* __restrict__ gamma,
                        const float* __restrict__ beta) {
    __shared__ float s_acc[128];
    int tid = threadIdx.x;
    int lane = tid & 31;
    if (tid < 128) s_acc[tid] = 0.0f;
    __syncthreads();

    int f0 = 2 * lane, f1 = 2 * lane + 1;
    float mux = d_sum_s[f0] / (float)NE;
    float muy = d_sum_s[f1] / (float)NE;
    float isx = rsqrtf(d_ss_s[f0] / (float)NE - mux * mux + 1e-5f);
    float isy = rsqrtf(d_ss_s[f1] / (float)NE - muy * muy + 1e-5f);
    float ax = isx * gamma[f0], ay = isy * gamma[f1];
    float cx = beta[f0] - mux * ax, cy = beta[f1] - muy * ay;

    int warp = (blockIdx.x * blockDim.x + tid) >> 5;
    int nwarp = (gridDim.x * blockDim.x) >> 5;
    float nsx = 0.f, nsy = 0.f, nqx = 0.f, nqy = 0.f;

    for (int n = warp; n < NN; n += nwarp) {
        int beg = d_row[n], end = d_row[n + 1];
        float2 bs = *(const float2*)&g_bsum[n * 64 + f0];
        float accx = 0.f, accy = 0.f;
        int e = beg;
        for (; e + 1 < end; e += 2) {
            int ei0 = d_ei[e], ei1 = d_ei[e + 1];
            float2 es0 = *(const float2*)&g_esum[ei0 * 64 + f0];
            float2 es1 = *(const float2*)&g_esum[ei1 * 64 + f0];
            accx += fmaxf(0.f, fmaf(bs.x + es0.x, ax, cx))
                  + fmaxf(0.f, fmaf(bs.x + es1.x, ax, cx));
            accy += fmaxf(0.f, fmaf(bs.y + es0.y, ay, cy))
                  + fmaxf(0.f, fmaf(bs.y + es1.y, ay, cy));
        }
        if (e < end) {
            int ei0 = d_ei[e];
            float2 es0 = *(const float2*)&g_esum[ei0 * 64 + f0];
            accx += fmaxf(0.f, fmaf(bs.x + es0.x, ax, cx));
            accy += fmaxf(0.f, fmaf(bs.y + es0.y, ay, cy));
        }
        float2 o; o.x = accx; o.y = accy;
        *(float2*)&g_sumagg[n * 64 + f0] = o;
        nsx += accx; nsy += accy;
        nqx += accx * accx; nqy += accy * accy;
    }

    atomicAdd(&s_acc[f0], nsx);
    atomicAdd(&s_acc[f1], nsy);
    atomicAdd(&s_acc[64 + f0], nqx);
    atomicAdd(&s_acc[64 + f1], nqy);
    __syncthreads();
    if (tid < 64) {
        atomicAdd(&d_sum_g[64 + tid], s_acc[tid]);
        atomicAdd(&d_ss_g[64 + tid], s_acc[64 + tid]);
    }
}

// ---- K5: empty-segment fix + node-BN stats for segmax half ----
__global__ void k_node() {
    __shared__ float s_acc[128];
    int tid = threadIdx.x;
    int lane = tid & 31;
    if (tid < 128) s_acc[tid] = 0.0f;
    __syncthreads();

    int f0 = 2 * lane;
    float minv = fdec(d_min_i);
    int warp = (blockIdx.x * blockDim.x + tid) >> 5;
    int nwarp = (gridDim.x * blockDim.x) >> 5;
    float nsx = 0.f, nsy = 0.f, nqx = 0.f, nqy = 0.f;
    for (int n = warp; n < NN; n += nwarp) {
        float2 v = *(const float2*)&g_segmax[n * 64 + f0];
        if (v.x == -INFINITY) {
            v.x = minv; v.y = minv;
            *(float2*)&g_segmax[n * 64 + f0] = v;
        }
        nsx += v.x; nsy += v.y;
        nqx += v.x * v.x; nqy += v.y * v.y;
    }
    atomicAdd(&s_acc[f0], nsx);
    atomicAdd(&s_acc[f0 + 1], nsy);
    atomicAdd(&s_acc[64 + f0], nqx);
    atomicAdd(&s_acc[64 + f0 + 1], nqy);
    __syncthreads();
    if (tid < 64) {
        atomicAdd(&d_sum_g[tid], s_acc[tid]);
        atomicAdd(&d_ss_g[tid], s_acc[64 + tid]);
    }
}

// ---- K6: finalize node-BN; pack BN-folded W_u into fragment order + doff ----
__global__ void k_fin_g(const float* __restrict__ gamma_u,
                        const float* __restrict__ beta_u,
                        const float* __restrict__ W_u) {
    int t = threadIdx.x;  // 256
    if (t < 128) {
        float mu = d_sum_g[t] / (float)NN;
        float var = d_ss_g[t] / (float)NN - mu * mu;
        float a = rsqrtf(var + 1e-5f) * gamma_u[t];
        d_a_g[t] = a;
        d_c_g[t] = beta_u[t] - mu * a;
    }
    __syncthreads();
    // pack W' = a.W into fragment lane order (4096 float2 entries)
    for (int e = t; e < 8 * 2 * 8 * 32; e += 256) {
        int lane = e & 31;
        int t2 = e >> 5;
        int nbk = t2 & 7;
        int ks = (t2 >> 3) & 1;
        int kc = t2 >> 4;
        int g = lane >> 2, tig = lane & 3;
        int k = kc * 16 + ks * 8 + tig;
        int n = nbk * 8 + g;
        float2 v;
        v.x = to_tf32(d_a_g[k] * W_u[k * 64 + n]);
        v.y = to_tf32(d_a_g[k + 4] * W_u[(k + 4) * 64 + n]);
        *(float2*)&d_W2[e * 2] = v;
    }
    if (t < 64) {
        float acc = 0.f;
        for (int k = 0; k < 128; k++) acc += d_c_g[k] * W_u[k * 64 + t];
        d_doff[t] = acc;
    }
}

// ---- K7: GEMM2 tf32 mma: out = self + relu([segmax|sumagg] @ W' + doff) ----
__global__ void __launch_bounds__(256, 2)
k_final(float* __restrict__ out) {
    __shared__ __align__(16) float As[2][256][20];
    int tid = threadIdx.x;
    int lane = tid & 31, wid = tid >> 5;
    int wm = wid & 3, wn = wid >> 2;
    int g = lane >> 2, tig = lane & 3;
    int m0 = blockIdx.x * 256;

    float c[4][4][4];
    #pragma unroll
    for (int mt = 0; mt < 4; mt++)
        #pragma unroll
        for (int nt = 0; nt < 4; nt++)
            #pragma unroll
            for (int i = 0; i < 4; i++) c[mt][nt][i] = 0.0f;

    int frow = tid >> 2;
    int fc = (tid & 3) * 4;

    // chunk kci covers k = kci*16 + [0,16): chunks 0-3 from segmax, 4-7 from sumagg
    #pragma unroll
    for (int p = 0; p < 4; p++) {
        int gm = m0 + p * 64 + frow;
        float4 v = make_float4(0.f, 0.f, 0.f, 0.f);
        if (gm < NN) v = *(const float4*)&g_segmax[gm * 64 + fc];
        *(float4*)&As[0][p * 64 + frow][fc] = to_tf32_4(v);
    }
    __syncthreads();

    #pragma unroll
    for (int kci = 0; kci < 8; kci++) {
        int cur = kci & 1;
        float4 pf[4];
        if (kci < 7) {
            int kg = (kci + 1) * 16 + fc;   // global k of prefetch
            const float* src = (kg < 64) ? g_segmax : g_sumagg;
            int off = (kg < 64) ? kg : (kg - 64);
            #pragma unroll
            for (int p = 0; p < 4; p++) {
                int gm = m0 + p * 64 + frow;
                pf[p] = make_float4(0.f, 0.f, 0.f, 0.f);
                if (gm < NN) pf[p] = *(const float4*)&src[gm * 64 + off];
            }
        }

        #pragma unroll
        for (int ks = 0; ks < 2; ks++) {
            int kk = ks * 8 + tig;
            unsigned af[4][4];
            #pragma unroll
            for (int mt = 0; mt < 4; mt++) {
                int mr = wm * 64 + mt * 16;
                af[mt][0] = __float_as_uint(As[cur][mr + g][kk]);
                af[mt][1] = __float_as_uint(As[cur][mr + g + 8][kk]);
                af[mt][2] = __float_as_uint(As[cur][mr + g][kk + 4]);
                af[mt][3] = __float_as_uint(As[cur][mr + g + 8][kk + 4]);
            }
            #pragma unroll
            for (int nt = 0; nt < 4; nt++) {
                int nbk = wn * 4 + nt;
                float2 bf = *(const float2*)&d_W2[(((kci * 2) + ks) * 8 + nbk) * 64 + lane * 2];
                unsigned b0 = __float_as_uint(bf.x);
                unsigned b1 = __float_as_uint(bf.y);
                #pragma unroll
                for (int mt = 0; mt < 4; mt++) {
                    asm volatile(
                        "mma.sync.aligned.m16n8k8.row.col.f32.tf32.tf32.f32 "
                        "{%0,%1,%2,%3}, {%4,%5,%6,%7}, {%8,%9}, {%0,%1,%2,%3};"
                        : "+f"(c[mt][nt][0]), "+f"(c[mt][nt][1]),
                          "+f"(c[mt][nt][2]), "+f"(c[mt][nt][3])
                        : "r"(af[mt][0]), "r"(af[mt][1]), "r"(af[mt][2]), "r"(af[mt][3]),
                          "r"(b0), "r"(b1));
                }
            }
        }

        if (kci < 7) {
            #pragma unroll
            for (int p = 0; p < 4; p++)
                *(float4*)&As[cur ^ 1][p * 64 + frow][fc] = to_tf32_4(pf[p]);
        }
        __syncthreads();
    }

    #pragma unroll
    for (int mt = 0; mt < 4; mt++) {
        #pragma unroll
        for (int nt = 0; nt < 4; nt++) {
            int col = wn * 32 + nt * 8 + tig * 2;
            float dx = d_doff[col], dy = d_doff[col + 1];
            int r0 = m0 + wm * 64 + mt * 16 + g;
            if (r0 < NN) {
                float2 sf = *(const float2*)&g_self[r0 * 64 + col];
                float2 o;
                o.x = sf.x + fmaxf(0.f, c[mt][nt][0] + dx);
                o.y = sf.y + fmaxf(0.f, c[mt][nt][1] + dy);
                *(float2*)&out[r0 * 64 + col] = o;
            }
            int r1 = r0 + 8;
            if (r1 < NN) {
                float2 sf = *(const float2*)&g_self[r1 * 64 + col];
                float2 o;
                o.x = sf.x + fmaxf(0.f, c[mt][nt][2] + dx);
                o.y = sf.y + fmaxf(0.f, c[mt][nt][3] + dy);
                *(float2*)&out[r1 * 64 + col] = o;
            }
        }
    }
}

extern "C" void kernel_launch(void* const* d_in, const int* in_sizes, int n_in,
                              void* d_out, int out_size) {
    const float* n_feat  = (const float*)d_in[0];
    const int*   eidx    = (const int*)d_in[1];
    const float* W_b     = (const float*)d_in[2];
    const float* b_b     = (const float*)d_in[3];
    const float* gamma_g = (const float*)d_in[4];
    const float* beta_g  = (const float*)d_in[5];
    const float* gamma_u = (const float*)d_in[6];
    const float* beta_u  = (const float*)d_in[7];
    const float* W_u     = (const float*)d_in[8];
    float* out           = (float*)d_out;

    const int* begin_ids = eidx;
    const int* end_ids   = eidx + NE;

    // lazily create side stream + events on first (uncaptured) call
    static cudaStream_t s1 = 0;
    static cudaEvent_t evFork = 0, evJoin = 0, evFork2 = 0, evJoin2 = 0;
    if (!s1) {
        cudaStreamCreateWithFlags(&s1, cudaStreamNonBlocking);
        cudaEventCreateWithFlags(&evFork, cudaEventDisableTiming);
        cudaEventCreateWithFlags(&evJoin, cudaEventDisableTiming);
        cudaEventCreateWithFlags(&evFork2, cudaEventDisableTiming);
        cudaEventCreateWithFlags(&evJoin2, cudaEventDisableTiming);
    }

    // fork: GEMM chain on s1, CSR chain on default stream — independent
    cudaEventRecord(evFork, 0);
    cudaStreamWaitEvent(s1, evFork, 0);
    k_prepB<<<160, 256, 0, s1>>>(W_b);
    dim3 g1((NN + 255) / 256, 5);
    k_gemm1<<<g1, 256, 0, s1>>>(n_feat, b_b);

    k_init<<<256, 256>>>();
    k_deg<<<1184, 256>>>(begin_ids);
    k_scan1<<<NBLK, SCAN_B>>>();
    k_scan2<<<1, 128>>>();
    k_scan3<<<NBLK, SCAN_B>>>();
    k_fill<<<1184, 256>>>(begin_ids, end_ids);

    // join: edgeA needs both GEMM outputs and CSR
    cudaEventRecord(evJoin, s1);
    cudaStreamWaitEvent(0, evJoin, 0);
    k_edgeA<<<1184, 256>>>();

    // fork 2: k_node (needs only edgeA) overlaps edgeB (disjoint d_sum_g halves)
    cudaEventRecord(evFork2, 0);
    cudaStreamWaitEvent(s1, evFork2, 0);
    k_node<<<1184, 256, 0, s1>>>();

    k_edgeB<<<1184, 256>>>(gamma_g, beta_g);

    cudaEventRecord(evJoin2, s1);
    cudaStreamWaitEvent(0, evJoin2, 0);
    k_fin_g<<<1, 256>>>(gamma_u, beta_u, W_u);
    k_final<<<(NN + 255) / 256, 256>>>(out);
}